// round 13
// baseline (speedup 1.0000x reference)
#include <cuda_runtime.h>
#include <math.h>

// Problem dims
#define TT 256
#define BB 64
#define EE 768
#define HH 512
#define H2 1024
#define GG 2048            // 4*H
#define TB (TT*BB)         // 16384

// ---------------- scratch (device globals; no allocation allowed) ----------
__device__ float g_pre[2][(size_t)BB*TT*GG];   // [dir][b][t][g]  (bias included)
__device__ float g_h[2][2][TT*HH];             // [pingpong][dir][t*H+j]
__device__ float g_sents[(size_t)TB*H2];       // [t][b][h2]
__device__ float g_hW[(size_t)TB*H2];          // [t][b][k]
__device__ float g_WnovT[(size_t)H2*H2];       // W_nov transposed (K-major)
__device__ float g_docmean[BB*H2];
__device__ float g_doc[BB*H2];
__device__ float g_u[BB*H2];
__device__ float g_absp[TT];
__device__ float g_s0[BB*TT];

// per-group barrier state (4 groups of 32 blocks; reset by k_zero)
__device__ unsigned g_bar_count[4];
__device__ unsigned g_bar_gen[4];
#define GRPBLK 32

// =========================================================================
// mma.sync 3xTF32 GEMM machinery (mask-based fast split)
// =========================================================================
#define LDSS 36                         // smem row stride (floats)
#define TILE_F (128*LDSS)
#define SMEM_G (6*TILE_F*4)             // big GEMM: 3 stages x (A+B) = 110592 B

// persistent rec: W tile 16 chunks x 64 rows x LDSS + 4 A bufs (2 stages x 2)
#define WCHUNK_F (64*LDSS)              // 2304 floats per W chunk
#define W_F      (16*WCHUNK_F)          // 36864 floats = 147456 B
#define ABUF_F   (128*LDSS)             // 4608 floats = 18432 B
#define SMEM_RP  ((W_F + 4*ABUF_F)*4)   // 221184 B

__device__ __forceinline__ unsigned smem_u32(const void* p) {
    unsigned a;
    asm("{ .reg .u64 t; cvta.to.shared.u64 t, %1; cvt.u32.u64 %0, t; }"
        : "=r"(a) : "l"(p));
    return a;
}
__device__ __forceinline__ void cp16(unsigned s, const float* g) {
    asm volatile("cp.async.cg.shared.global [%0], [%1], 16;"
                 :: "r"(s), "l"(__cvta_generic_to_global((void*)g)));
}
__device__ __forceinline__ void cp_commit() {
    asm volatile("cp.async.commit_group;" ::: "memory");
}
__device__ __forceinline__ void cp_wait1() {
    asm volatile("cp.async.wait_group 1;" ::: "memory");
}
__device__ __forceinline__ void cp_wait0() {
    asm volatile("cp.async.wait_group 0;" ::: "memory");
}
__device__ __forceinline__ void l2_prefetch(const float* p) {
    asm volatile("prefetch.global.L2 [%0];" :: "l"(p));
}
__device__ __forceinline__ void mma8(float c[4], const unsigned a[4], const unsigned b[2]) {
    asm volatile(
        "mma.sync.aligned.m16n8k8.row.col.f32.tf32.tf32.f32 "
        "{%0,%1,%2,%3}, {%4,%5,%6,%7}, {%8,%9}, {%0,%1,%2,%3};\n"
        : "+f"(c[0]), "+f"(c[1]), "+f"(c[2]), "+f"(c[3])
        : "r"(a[0]), "r"(a[1]), "r"(a[2]), "r"(a[3]), "r"(b[0]), "r"(b[1]));
}
// fast split: hi = f masked to tf32 mantissa; lo = exact residual
__device__ __forceinline__ void split_tf32(float f, unsigned& hi, unsigned& lo) {
    hi = __float_as_uint(f) & 0xffffe000u;
    lo = __float_as_uint(f - __uint_as_float(hi));
}
// fast saturating sigmoid/tanh via __expf (no inf/inf hazard)
__device__ __forceinline__ float fsig(float x) {
    return 1.f / (1.f + __expf(-x));
}
__device__ __forceinline__ float ftanh(float x) {
    return 1.f - 2.f / (__expf(2.f * x) + 1.f);
}

// load a 128-row x 32-float K-chunk into smem tile (256 threads)
__device__ __forceinline__ void load_chunk(const float* __restrict__ gsrc, int ldg,
                                           unsigned sbase, int tid) {
    int r0 = tid >> 3;
    int c  = (tid & 7) * 4;
    const float* gp = gsrc + (size_t)r0 * ldg + c;
    unsigned sp = sbase + (unsigned)((r0 * LDSS + c) * 4);
    #pragma unroll
    for (int q = 0; q < 4; q++) {
        cp16(sp, gp);
        gp += (size_t)32 * ldg;
        sp += 32 * LDSS * 4;
    }
}

// 256-thread compute: warp tile 64x32 (wm 0..1, wn 0..3) for big GEMM
__device__ __forceinline__ void compute_chunk(const float* sA, const float* sB,
                                              int wm, int wn, int lane,
                                              float acc[4][4][4]) {
    int g = lane >> 2, tig = lane & 3;
    #pragma unroll
    for (int kk = 0; kk < 4; kk++) {
        int k0 = kk * 8 + tig;
        unsigned ah[4][4], al[4][4], bh[4][2], bl[4][2];
        #pragma unroll
        for (int mi = 0; mi < 4; mi++) {
            int ar = wm * 64 + mi * 16 + g;
            split_tf32(sA[ar * LDSS + k0],           ah[mi][0], al[mi][0]);
            split_tf32(sA[(ar + 8) * LDSS + k0],     ah[mi][1], al[mi][1]);
            split_tf32(sA[ar * LDSS + k0 + 4],       ah[mi][2], al[mi][2]);
            split_tf32(sA[(ar + 8) * LDSS + k0 + 4], ah[mi][3], al[mi][3]);
        }
        #pragma unroll
        for (int ni = 0; ni < 4; ni++) {
            int bn = wn * 32 + ni * 8 + g;
            split_tf32(sB[bn * LDSS + k0],     bh[ni][0], bl[ni][0]);
            split_tf32(sB[bn * LDSS + k0 + 4], bh[ni][1], bl[ni][1]);
        }
        #pragma unroll
        for (int mi = 0; mi < 4; mi++)
            #pragma unroll
            for (int ni = 0; ni < 4; ni++) {
                mma8(acc[mi][ni], al[mi], bh[ni]);
                mma8(acc[mi][ni], ah[mi], bl[ni]);
                mma8(acc[mi][ni], ah[mi], bh[ni]);
            }
    }
}

// rec compute: warp tile 64x32 with split-K (kq warps each take 2 of 4 kk)
__device__ __forceinline__ void compute_rec(const float* sA, const float* sB,
                                            int wm, int wn, int kq, int lane,
                                            float acc[4][4][4]) {
    int g = lane >> 2, tig = lane & 3;
    #pragma unroll
    for (int kh = 0; kh < 2; kh++) {
        int k0 = (kq * 2 + kh) * 8 + tig;
        unsigned ah[4][4], al[4][4], bh[4][2], bl[4][2];
        #pragma unroll
        for (int mi = 0; mi < 4; mi++) {
            int ar = wm * 64 + mi * 16 + g;
            split_tf32(sA[ar * LDSS + k0],           ah[mi][0], al[mi][0]);
            split_tf32(sA[(ar + 8) * LDSS + k0],     ah[mi][1], al[mi][1]);
            split_tf32(sA[ar * LDSS + k0 + 4],       ah[mi][2], al[mi][2]);
            split_tf32(sA[(ar + 8) * LDSS + k0 + 4], ah[mi][3], al[mi][3]);
        }
        #pragma unroll
        for (int ni = 0; ni < 4; ni++) {
            int bn = wn * 32 + ni * 8 + g;
            split_tf32(sB[bn * LDSS + k0],     bh[ni][0], bl[ni][0]);
            split_tf32(sB[bn * LDSS + k0 + 4], bh[ni][1], bl[ni][1]);
        }
        #pragma unroll
        for (int mi = 0; mi < 4; mi++)
            #pragma unroll
            for (int ni = 0; ni < 4; ni++) {
                mma8(acc[mi][ni], al[mi], bh[ni]);
                mma8(acc[mi][ni], ah[mi], bl[ni]);
                mma8(acc[mi][ni], ah[mi], bh[ni]);
            }
    }
}

// ---------------- parallel GEMMs ---------------------------------------------
// mode 0: fused input projections, grid.z = dir; mode 2: novelty GEMM
// 3-stage cp.async pipeline, ONE __syncthreads per K-chunk.
__global__ void __launch_bounds__(256, 2) k_mma_gemm(
    const float* __restrict__ A,
    const float* __restrict__ W0,
    const float* __restrict__ W1,
    const float* __restrict__ bias0,
    const float* __restrict__ bias1,
    int K, int mode)
{
    extern __shared__ __align__(16) float sm[];
    int dir = blockIdx.z;
    const float* W;
    const float* bias;
    if (mode == 2) { A = &g_sents[0]; W = &g_WnovT[0]; bias = nullptr; }
    else           { W = dir ? W1 : W0; bias = dir ? bias1 : bias0; }

    float*   sA[3]; float*   sB[3];
    unsigned uA[3]; unsigned uB[3];
    #pragma unroll
    for (int st = 0; st < 3; st++) {
        sA[st] = sm + st * 2 * TILE_F;
        sB[st] = sA[st] + TILE_F;
        uA[st] = smem_u32(sA[st]);
        uB[st] = smem_u32(sB[st]);
    }
    int tid = threadIdx.x, lane = tid & 31, wid = tid >> 5;
    int wm = wid >> 2, wn = wid & 3;
    int n0 = blockIdx.x * 128, m0 = blockIdx.y * 128;
    const float* Ab = A + (size_t)m0 * K;
    const float* Wb = W + (size_t)n0 * K;

    float acc[4][4][4];
    #pragma unroll
    for (int i = 0; i < 4; i++)
        #pragma unroll
        for (int j = 0; j < 4; j++)
            #pragma unroll
            for (int q = 0; q < 4; q++) acc[i][j][q] = 0.f;

    int NC = K >> 5;
    load_chunk(Ab,      K, uA[0], tid); load_chunk(Wb,      K, uB[0], tid); cp_commit();
    load_chunk(Ab + 32, K, uA[1], tid); load_chunk(Wb + 32, K, uB[1], tid); cp_commit();

    for (int i = 0; i < NC; i++) {
        if (i == NC - 1) cp_wait0(); else cp_wait1();
        __syncthreads();
        if (i + 2 < NC) {
            int st = (i + 2) % 3;
            size_t o = (size_t)(i + 2) * 32;
            load_chunk(Ab + o, K, uA[st], tid);
            load_chunk(Wb + o, K, uB[st], tid);
            cp_commit();
        }
        int p = i % 3;
        compute_chunk(sA[p], sB[p], wm, wn, lane, acc);
    }

    int g = lane >> 2, tig = lane & 3;
    #pragma unroll
    for (int mi = 0; mi < 4; mi++) {
        #pragma unroll
        for (int ni = 0; ni < 4; ni++) {
            int n = n0 + wn * 32 + ni * 8 + tig * 2;
            float2 bs = make_float2(0.f, 0.f);
            if (bias) bs = *(const float2*)(bias + n);
            #pragma unroll
            for (int hf = 0; hf < 2; hf++) {
                int m = m0 + wm * 64 + mi * 16 + g + hf * 8;
                float2 v = make_float2(acc[mi][ni][hf * 2 + 0] + bs.x,
                                       acc[mi][ni][hf * 2 + 1] + bs.y);
                if (mode < 2) {
                    int t = m >> 6, b = m & 63;
                    *(float2*)&g_pre[dir][(((size_t)b * TT + t) * GG) + n] = v;
                } else {
                    *(float2*)&g_hW[(size_t)m * H2 + n] = v;
                }
            }
        }
    }
}

// ---------------- per-group software barrier ---------------------------------
__device__ __forceinline__ void grid_bar(int grp, unsigned gen) {
    __threadfence();
    __syncthreads();
    if (threadIdx.x == 0) {
        unsigned arrived = atomicAdd(&g_bar_count[grp], 1u) + 1u;
        if (arrived == GRPBLK) {
            g_bar_count[grp] = 0u;
            __threadfence();
            atomicExch(&g_bar_gen[grp], gen + 1u);
        } else {
            while (atomicAdd(&g_bar_gen[grp], 0u) <= gen) __nanosleep(20);
        }
    }
    __syncthreads();
}

// ---------------- persistent recurrence kernel, W resident in SMEM ----------
// 128 blocks (32 j-tiles x 2 t-tiles x 2 dirs), 256 threads, 64 steps.
// 8 warps = 2m x 2n x 2kq (split-K). A streamed in 64-wide super-chunks.
// Barrier is per (dir,t-tile) group of 32 blocks (the only h dependency).
#define GBSR 68
__global__ void __launch_bounds__(256) k_mma_rec_p(
    const float* __restrict__ w_hh_f,
    const float* __restrict__ w_hh_b)
{
    extern __shared__ __align__(16) float sm[];
    int dir = blockIdx.z;
    const float* W = dir ? w_hh_b : w_hh_f;
    int j0 = blockIdx.x * 16;
    int m0 = blockIdx.y * 128;
    int grp = dir * 2 + blockIdx.y;
    int tid = threadIdx.x, lane = tid & 31, wid = tid >> 5;
    int wm = wid >> 2;          // 0..1 : 64-row M half
    int wn = (wid >> 1) & 1;    // 0..1 : 32-col N half
    int kq = wid & 1;           // 0..1 : K split

    float* sW = sm;                     // 16 chunks x 64 x LDSS
    float* sA[4];
    unsigned uA[4];
    #pragma unroll
    for (int st = 0; st < 4; st++) {
        sA[st] = sm + W_F + st * ABUF_F;
        uA[st] = smem_u32(sA[st]);
    }
    float* gb = sm + W_F;               // epilogue gate buffer aliases A bufs

    // ---- load W once: 16 chunks, gate-grouped rows ----
    {
        #pragma unroll
        for (int chunk = 0; chunk < 16; chunk++) {
            unsigned base = smem_u32(sW + chunk * WCHUNK_F);
            #pragma unroll
            for (int q = 0; q < 2; q++) {
                int idx = q * 256 + tid;
                int row = idx >> 3;
                int c   = (idx & 7) * 4;
                int grow = (row >> 4) * 512 + j0 + (row & 15);
                cp16(base + (unsigned)((row * LDSS + c) * 4),
                     W + (size_t)grow * HH + chunk * 32 + c);
            }
        }
        cp_commit(); cp_wait0();
        __syncthreads();
    }

    float creg[8];
    #pragma unroll
    for (int q = 0; q < 8; q++) creg[q] = 0.f;

    for (int s = 0; s < BB; s++) {
        int pp = s & 1;
        int b = dir ? (BB - 1 - s) : s;
        const float* Ab = &g_h[pp][dir][0] + (size_t)m0 * HH;

        // L2-prefetch this step's g_pre gate lines (consumed in the epilogue)
        #pragma unroll
        for (int q = 0; q < 2; q++) {
            int idx = tid + q * 256;
            int tl = idx >> 2, gate = idx & 3;
            l2_prefetch(&g_pre[dir][(((size_t)b * TT + m0 + tl) * GG) + gate * 512 + j0]);
        }

        float acc[4][4][4];
        #pragma unroll
        for (int i = 0; i < 4; i++)
            #pragma unroll
            for (int j = 0; j < 4; j++)
                #pragma unroll
                for (int q = 0; q < 4; q++) acc[i][j][q] = 0.f;

        // preload super-chunk 0 (chunks 0,1)
        load_chunk(Ab,      HH, uA[0], tid);
        load_chunk(Ab + 32, HH, uA[1], tid);
        cp_commit();

        #pragma unroll 2
        for (int sc = 0; sc < 8; sc++) {
            cp_wait0();
            __syncthreads();
            if (sc + 1 < 8) {
                int nb = ((sc + 1) & 1) * 2;
                load_chunk(Ab + (sc + 1) * 64,      HH, uA[nb],     tid);
                load_chunk(Ab + (sc + 1) * 64 + 32, HH, uA[nb + 1], tid);
                cp_commit();
            }
            int pb = (sc & 1) * 2;
            compute_rec(sA[pb],     sW + (2 * sc)     * WCHUNK_F, wm, wn, kq, lane, acc);
            compute_rec(sA[pb + 1], sW + (2 * sc + 1) * WCHUNK_F, wm, wn, kq, lane, acc);
        }
        __syncthreads();

        // combine split-K partials in smem gate buffer:
        int g = lane >> 2, tig = lane & 3;
        if (kq == 0) {
            #pragma unroll
            for (int mi = 0; mi < 4; mi++) {
                #pragma unroll
                for (int ni = 0; ni < 4; ni++) {
                    int col = wn * 32 + ni * 8 + tig * 2;
                    #pragma unroll
                    for (int hf = 0; hf < 2; hf++) {
                        int row = wm * 64 + mi * 16 + g + hf * 8;
                        gb[row * GBSR + col]     = acc[mi][ni][hf * 2 + 0];
                        gb[row * GBSR + col + 1] = acc[mi][ni][hf * 2 + 1];
                    }
                }
            }
        }
        __syncthreads();
        if (kq == 1) {
            #pragma unroll
            for (int mi = 0; mi < 4; mi++) {
                #pragma unroll
                for (int ni = 0; ni < 4; ni++) {
                    int col = wn * 32 + ni * 8 + tig * 2;
                    #pragma unroll
                    for (int hf = 0; hf < 2; hf++) {
                        int row = wm * 64 + mi * 16 + g + hf * 8;
                        gb[row * GBSR + col]     += acc[mi][ni][hf * 2 + 0];
                        gb[row * GBSR + col + 1] += acc[mi][ni][hf * 2 + 1];
                    }
                }
            }
        }
        __syncthreads();

        // fused LSTM cell update: 128 t x 16 j items, 8 per thread, c in regs
        #pragma unroll
        for (int it = 0; it < 8; it++) {
            int id = tid + it * 256;
            int tl = id >> 4, jj = id & 15;
            int tg = m0 + tl;
            int jg = j0 + jj;
            size_t preb = ((size_t)b * TT + tg) * GG;
            float vi = gb[tl * GBSR +  0 + jj] + g_pre[dir][preb +    0 + jg];
            float vf = gb[tl * GBSR + 16 + jj] + g_pre[dir][preb +  512 + jg];
            float vg = gb[tl * GBSR + 32 + jj] + g_pre[dir][preb + 1024 + jg];
            float vo = gb[tl * GBSR + 48 + jj] + g_pre[dir][preb + 1536 + jg];
            float c  = creg[it];
            float si = fsig(vi);
            float sf = fsig(vf);
            float so = fsig(vo);
            float cn = sf * c + si * ftanh(vg);
            float h  = so * ftanh(cn);
            creg[it] = cn;
            g_h[pp ^ 1][dir][tg * HH + jg] = h;
            g_sents[(((size_t)tg * BB + b) * H2) + dir * HH + jg] = h;
        }

        if (s + 1 < BB) grid_bar(grp, (unsigned)s);
    }
}

// ---------------- transpose W_nov (K-major B for the nn GEMM) ---------------
__global__ void k_transpose(const float* __restrict__ W) {
    __shared__ float ts[32][33];
    int bx = blockIdx.x * 32, by = blockIdx.y * 32;
    int tx = threadIdx.x, ty = threadIdx.y;   // 32 x 8
    #pragma unroll
    for (int q = 0; q < 4; q++)
        ts[ty + 8*q][tx] = W[(size_t)(by + ty + 8*q) * H2 + bx + tx];
    __syncthreads();
    #pragma unroll
    for (int q = 0; q < 4; q++)
        g_WnovT[(size_t)(bx + ty + 8*q) * H2 + by + tx] = ts[tx][ty + 8*q];
}

// ---------------- init -----------------------------------------------------
__global__ void k_zero() {
    int i = blockIdx.x * blockDim.x + threadIdx.x;
    if (i < 4) { g_bar_count[i] = 0u; g_bar_gen[i] = 0u; }
    if (i < 2*TT*HH) {
        (&g_h[0][0][0])[i] = 0.f;    // pingpong slot 0, both dirs
    }
}

// ---------------- doc pipeline ----------------------------------------------
__global__ void k_docmean() {
    int idx = blockIdx.x * blockDim.x + threadIdx.x;
    int b = idx >> 10, h = idx & 1023;
    float s = 0.f;
    for (int t = 0; t < TT; t++) s += g_sents[(((size_t)t*BB + b)*H2) + h];
    g_docmean[b*H2 + h] = s * (1.f/TT);
}

__global__ void k_doc(const float* __restrict__ W_fdoc, const float* __restrict__ b_fdoc) {
    int w = blockIdx.x*8 + (threadIdx.x >> 5);
    int lane = threadIdx.x & 31;
    int b = w >> 10, n = w & 1023;
    const float* wr = &W_fdoc[(size_t)n*H2];
    const float* dm = &g_docmean[b*H2];
    float s = 0.f;
    for (int k = lane; k < H2; k += 32) s += wr[k]*dm[k];
    #pragma unroll
    for (int o = 16; o > 0; o >>= 1) s += __shfl_down_sync(0xffffffffu, s, o);
    if (lane == 0) g_doc[b*H2 + n] = ftanh(s + b_fdoc[n]);
}

__global__ void k_u(const float* __restrict__ W_sal, const float* __restrict__ w_content) {
    int w = blockIdx.x*8 + (threadIdx.x >> 5);
    int lane = threadIdx.x & 31;
    int b = w >> 10, h = w & 1023;
    const float* wr = &W_sal[(size_t)h*H2];
    const float* dc = &g_doc[b*H2];
    float s = 0.f;
    for (int k = lane; k < H2; k += 32) s += wr[k]*dc[k];
    #pragma unroll
    for (int o = 16; o > 0; o >>= 1) s += __shfl_down_sync(0xffffffffu, s, o);
    if (lane == 0) g_u[b*H2 + h] = s + w_content[h];
}

__global__ void k_absp(const float* __restrict__ pos_emb, const float* __restrict__ w_abs) {
    int t = threadIdx.x;
    float s = 0.f;
    for (int p = 0; p < 100; p++) s += pos_emb[t*100 + p]*w_abs[p];
    g_absp[t] = s;
}

__global__ void k_s0(const float* __restrict__ bias) {
    int w = blockIdx.x*8 + (threadIdx.x >> 5);
    int lane = threadIdx.x & 31;
    int b = w >> 8, t = w & 255;
    const float* sp = &g_sents[((size_t)t*BB + b)*H2];
    const float* up = &g_u[b*H2];
    float s = 0.f;
    for (int k = lane; k < H2; k += 32) s += sp[k]*up[k];
    #pragma unroll
    for (int o = 16; o > 0; o >>= 1) s += __shfl_down_sync(0xffffffffu, s, o);
    if (lane == 0) g_s0[b*TT + t] = s + g_absp[t] + bias[0];
}

// ---------------- final sequential scan (independent per b) -----------------
__global__ void k_scan(float* __restrict__ out) {
    __shared__ float summ[H2];
    __shared__ float red[8];
    __shared__ float probsh;
    int b = blockIdx.x;
    int tid = threadIdx.x;
    int lane = tid & 31, wrp = tid >> 5;
    #pragma unroll
    for (int q = 0; q < 4; q++) summ[tid + q*256] = 0.f;
    __syncthreads();
    for (int t = 0; t < TT; t++) {
        const float* hw = &g_hW[((size_t)t*BB + b)*H2];
        float part = 0.f;
        #pragma unroll
        for (int q = 0; q < 4; q++) {
            int k = tid + q*256;
            part += hw[k]*ftanh(summ[k]);
        }
        #pragma unroll
        for (int o = 16; o > 0; o >>= 1) part += __shfl_down_sync(0xffffffffu, part, o);
        if (lane == 0) red[wrp] = part;
        __syncthreads();
        if (tid == 0) {
            float nov = 0.f;
            #pragma unroll
            for (int r = 0; r < 8; r++) nov += red[r];
            float prob = fsig(g_s0[b*TT + t] - nov);
            out[b*TT + t] = prob;
            probsh = prob;
        }
        __syncthreads();
        float p = probsh;
        const float* sp = &g_sents[((size_t)t*BB + b)*H2];
        #pragma unroll
        for (int q = 0; q < 4; q++) {
            int k = tid + q*256;
            summ[k] += p * sp[k];
        }
        __syncthreads();
    }
}

// ---------------- launcher ---------------------------------------------------
extern "C" void kernel_launch(void* const* d_in, const int* in_sizes, int n_in,
                              void* d_out, int out_size) {
    const float* emb      = (const float*)d_in[0];
    const float* w_ih_f   = (const float*)d_in[2];
    const float* w_hh_f   = (const float*)d_in[3];
    const float* b_f      = (const float*)d_in[4];
    const float* w_ih_b   = (const float*)d_in[5];
    const float* w_hh_b   = (const float*)d_in[6];
    const float* b_b      = (const float*)d_in[7];
    const float* W_fdoc   = (const float*)d_in[8];
    const float* b_fdoc   = (const float*)d_in[9];
    const float* pos_emb  = (const float*)d_in[10];
    const float* w_content= (const float*)d_in[11];
    const float* W_sal    = (const float*)d_in[12];
    const float* W_nov    = (const float*)d_in[13];
    const float* w_abs    = (const float*)d_in[14];
    const float* bias     = (const float*)d_in[15];
    float* out = (float*)d_out;

    cudaFuncSetAttribute(k_mma_gemm,  cudaFuncAttributeMaxDynamicSharedMemorySize, SMEM_G);
    cudaFuncSetAttribute(k_mma_rec_p, cudaFuncAttributeMaxDynamicSharedMemorySize, SMEM_RP);

    k_zero<<<1024, 256>>>();
    k_transpose<<<dim3(32, 32), dim3(32, 8)>>>(W_nov);

    // input projections, both dirs fused in one launch (grid.z = dir)
    dim3 gpre(GG/128, TB/128, 2);          // 16 x 128 x 2
    k_mma_gemm<<<gpre, 256, SMEM_G>>>(emb, w_ih_f, w_ih_b, b_f, b_b, EE, 0);

    // recurrence: ONE persistent launch, W resident in SMEM, 64 steps
    dim3 grec(HH/16, TT/128, 2);           // 32 x 2 x 2 = 128 blocks
    k_mma_rec_p<<<grec, 256, SMEM_RP>>>(w_hh_f, w_hh_b);

    k_docmean<<<256, 256>>>();
    k_doc<<<8192, 256>>>(W_fdoc, b_fdoc);
    k_u<<<8192, 256>>>(W_sal, w_content);
    k_absp<<<1, 256>>>(pos_emb, w_abs);
    k_s0<<<2048, 256>>>(bias);

    // novelty GEMM
    dim3 gnn(H2/128, TB/128, 1);           // 8 x 128
    k_mma_gemm<<<gnn, 256, SMEM_G>>>(nullptr, nullptr, nullptr, nullptr, nullptr, H2, 2);

    k_scan<<<BB, 256>>>(out);
}

// round 14
// speedup vs baseline: 1.0132x; 1.0132x over previous
#include <cuda_runtime.h>
#include <math.h>

// Problem dims
#define TT 256
#define BB 64
#define EE 768
#define HH 512
#define H2 1024
#define GG 2048            // 4*H
#define TB (TT*BB)         // 16384

// ---------------- scratch (device globals; no allocation allowed) ----------
__device__ float g_pre[2][(size_t)BB*TT*GG];   // [dir][b][t][g]  (bias included)
__device__ float g_h[2][2][TT*HH];             // [pingpong][dir][t*H+j]
__device__ float g_sents[(size_t)TB*H2];       // [t][b][h2]
__device__ float g_hW[(size_t)TB*H2];          // [t][b][k]
__device__ float g_WnovT[(size_t)H2*H2];       // W_nov transposed (K-major)
__device__ float g_docmean[BB*H2];
__device__ float g_doc[BB*H2];
__device__ float g_u[BB*H2];
__device__ float g_absp[TT];
__device__ float g_s0[BB*TT];

// per-group barrier state (4 groups of 32 blocks; reset by k_zero)
__device__ unsigned g_bar_count[4];
__device__ unsigned g_bar_gen[4];
#define GRPBLK 32

// =========================================================================
// mma.sync 3xTF32 GEMM machinery (mask-based fast split)
// =========================================================================
#define LDSS 36                         // smem row stride (floats)
#define TILE_F (128*LDSS)
#define SMEM_G (6*TILE_F*4)             // big GEMM: 3 stages x (A+B) = 110592 B

// persistent rec: W tile 16 chunks x 64 rows x LDSS + 4 A bufs (2 stages x 2)
#define WCHUNK_F (64*LDSS)              // 2304 floats per W chunk
#define W_F      (16*WCHUNK_F)          // 36864 floats = 147456 B
#define ABUF_F   (128*LDSS)             // 4608 floats = 18432 B
#define SMEM_RP  ((W_F + 4*ABUF_F)*4)   // 221184 B
#define GBSR 68
#define PBUF_F (128*GBSR)               // 8704 floats = 34816 B (x2 fits A bufs)

__device__ __forceinline__ unsigned smem_u32(const void* p) {
    unsigned a;
    asm("{ .reg .u64 t; cvta.to.shared.u64 t, %1; cvt.u32.u64 %0, t; }"
        : "=r"(a) : "l"(p));
    return a;
}
__device__ __forceinline__ void cp16(unsigned s, const float* g) {
    asm volatile("cp.async.cg.shared.global [%0], [%1], 16;"
                 :: "r"(s), "l"(__cvta_generic_to_global((void*)g)));
}
__device__ __forceinline__ void cp_commit() {
    asm volatile("cp.async.commit_group;" ::: "memory");
}
__device__ __forceinline__ void cp_wait1() {
    asm volatile("cp.async.wait_group 1;" ::: "memory");
}
__device__ __forceinline__ void cp_wait0() {
    asm volatile("cp.async.wait_group 0;" ::: "memory");
}
__device__ __forceinline__ void mma8(float c[4], const unsigned a[4], const unsigned b[2]) {
    asm volatile(
        "mma.sync.aligned.m16n8k8.row.col.f32.tf32.tf32.f32 "
        "{%0,%1,%2,%3}, {%4,%5,%6,%7}, {%8,%9}, {%0,%1,%2,%3};\n"
        : "+f"(c[0]), "+f"(c[1]), "+f"(c[2]), "+f"(c[3])
        : "r"(a[0]), "r"(a[1]), "r"(a[2]), "r"(a[3]), "r"(b[0]), "r"(b[1]));
}
// fast split: hi = f masked to tf32 mantissa; lo = exact residual
__device__ __forceinline__ void split_tf32(float f, unsigned& hi, unsigned& lo) {
    hi = __float_as_uint(f) & 0xffffe000u;
    lo = __float_as_uint(f - __uint_as_float(hi));
}
// fast saturating sigmoid/tanh via __expf (no inf/inf hazard)
__device__ __forceinline__ float fsig(float x) {
    return 1.f / (1.f + __expf(-x));
}
__device__ __forceinline__ float ftanh(float x) {
    return 1.f - 2.f / (__expf(2.f * x) + 1.f);
}

// load a 128-row x 32-float K-chunk into smem tile (256 threads)
__device__ __forceinline__ void load_chunk(const float* __restrict__ gsrc, int ldg,
                                           unsigned sbase, int tid) {
    int r0 = tid >> 3;
    int c  = (tid & 7) * 4;
    const float* gp = gsrc + (size_t)r0 * ldg + c;
    unsigned sp = sbase + (unsigned)((r0 * LDSS + c) * 4);
    #pragma unroll
    for (int q = 0; q < 4; q++) {
        cp16(sp, gp);
        gp += (size_t)32 * ldg;
        sp += 32 * LDSS * 4;
    }
}
// 128-row x 32-float chunk, 512 threads: 2 float4 per thread
__device__ __forceinline__ void load_chunk512(const float* __restrict__ gsrc, int ldg,
                                              unsigned sbase, int tid) {
    #pragma unroll
    for (int q = 0; q < 2; q++) {
        int idx = q * 512 + tid;
        int row = idx >> 3;
        int c   = (idx & 7) * 4;
        cp16(sbase + (unsigned)((row * LDSS + c) * 4),
             gsrc + (size_t)row * ldg + c);
    }
}

// 256-thread compute: warp tile 64x32 (wm 0..1, wn 0..3) for big GEMM
__device__ __forceinline__ void compute_chunk(const float* sA, const float* sB,
                                              int wm, int wn, int lane,
                                              float acc[4][4][4]) {
    int g = lane >> 2, tig = lane & 3;
    #pragma unroll
    for (int kk = 0; kk < 4; kk++) {
        int k0 = kk * 8 + tig;
        unsigned ah[4][4], al[4][4], bh[4][2], bl[4][2];
        #pragma unroll
        for (int mi = 0; mi < 4; mi++) {
            int ar = wm * 64 + mi * 16 + g;
            split_tf32(sA[ar * LDSS + k0],           ah[mi][0], al[mi][0]);
            split_tf32(sA[(ar + 8) * LDSS + k0],     ah[mi][1], al[mi][1]);
            split_tf32(sA[ar * LDSS + k0 + 4],       ah[mi][2], al[mi][2]);
            split_tf32(sA[(ar + 8) * LDSS + k0 + 4], ah[mi][3], al[mi][3]);
        }
        #pragma unroll
        for (int ni = 0; ni < 4; ni++) {
            int bn = wn * 32 + ni * 8 + g;
            split_tf32(sB[bn * LDSS + k0],     bh[ni][0], bl[ni][0]);
            split_tf32(sB[bn * LDSS + k0 + 4], bh[ni][1], bl[ni][1]);
        }
        #pragma unroll
        for (int mi = 0; mi < 4; mi++)
            #pragma unroll
            for (int ni = 0; ni < 4; ni++) {
                mma8(acc[mi][ni], al[mi], bh[ni]);
                mma8(acc[mi][ni], ah[mi], bl[ni]);
                mma8(acc[mi][ni], ah[mi], bh[ni]);
            }
    }
}

// rec compute: warp tile 64x32, 4-way split-K (warp kq takes kk slice kq)
__device__ __forceinline__ void compute_rec4(const float* sA, const float* sB,
                                             int wm, int wn, int kq, int lane,
                                             float acc[4][4][4]) {
    int g = lane >> 2, tig = lane & 3;
    int k0 = kq * 8 + tig;
    unsigned ah[4][4], al[4][4], bh[4][2], bl[4][2];
    #pragma unroll
    for (int mi = 0; mi < 4; mi++) {
        int ar = wm * 64 + mi * 16 + g;
        split_tf32(sA[ar * LDSS + k0],           ah[mi][0], al[mi][0]);
        split_tf32(sA[(ar + 8) * LDSS + k0],     ah[mi][1], al[mi][1]);
        split_tf32(sA[ar * LDSS + k0 + 4],       ah[mi][2], al[mi][2]);
        split_tf32(sA[(ar + 8) * LDSS + k0 + 4], ah[mi][3], al[mi][3]);
    }
    #pragma unroll
    for (int ni = 0; ni < 4; ni++) {
        int bn = wn * 32 + ni * 8 + g;
        split_tf32(sB[bn * LDSS + k0],     bh[ni][0], bl[ni][0]);
        split_tf32(sB[bn * LDSS + k0 + 4], bh[ni][1], bl[ni][1]);
    }
    #pragma unroll
    for (int mi = 0; mi < 4; mi++)
        #pragma unroll
        for (int ni = 0; ni < 4; ni++) {
            mma8(acc[mi][ni], al[mi], bh[ni]);
            mma8(acc[mi][ni], ah[mi], bl[ni]);
            mma8(acc[mi][ni], ah[mi], bh[ni]);
        }
}

// ---------------- parallel GEMMs ---------------------------------------------
// mode 0: fused input projections, grid.z = dir; mode 2: novelty GEMM
// 3-stage cp.async pipeline, ONE __syncthreads per K-chunk.
__global__ void __launch_bounds__(256, 2) k_mma_gemm(
    const float* __restrict__ A,
    const float* __restrict__ W0,
    const float* __restrict__ W1,
    const float* __restrict__ bias0,
    const float* __restrict__ bias1,
    int K, int mode)
{
    extern __shared__ __align__(16) float sm[];
    int dir = blockIdx.z;
    const float* W;
    const float* bias;
    if (mode == 2) { A = &g_sents[0]; W = &g_WnovT[0]; bias = nullptr; }
    else           { W = dir ? W1 : W0; bias = dir ? bias1 : bias0; }

    float*   sA[3]; float*   sB[3];
    unsigned uA[3]; unsigned uB[3];
    #pragma unroll
    for (int st = 0; st < 3; st++) {
        sA[st] = sm + st * 2 * TILE_F;
        sB[st] = sA[st] + TILE_F;
        uA[st] = smem_u32(sA[st]);
        uB[st] = smem_u32(sB[st]);
    }
    int tid = threadIdx.x, lane = tid & 31, wid = tid >> 5;
    int wm = wid >> 2, wn = wid & 3;
    int n0 = blockIdx.x * 128, m0 = blockIdx.y * 128;
    const float* Ab = A + (size_t)m0 * K;
    const float* Wb = W + (size_t)n0 * K;

    float acc[4][4][4];
    #pragma unroll
    for (int i = 0; i < 4; i++)
        #pragma unroll
        for (int j = 0; j < 4; j++)
            #pragma unroll
            for (int q = 0; q < 4; q++) acc[i][j][q] = 0.f;

    int NC = K >> 5;
    load_chunk(Ab,      K, uA[0], tid); load_chunk(Wb,      K, uB[0], tid); cp_commit();
    load_chunk(Ab + 32, K, uA[1], tid); load_chunk(Wb + 32, K, uB[1], tid); cp_commit();

    for (int i = 0; i < NC; i++) {
        if (i == NC - 1) cp_wait0(); else cp_wait1();
        __syncthreads();
        if (i + 2 < NC) {
            int st = (i + 2) % 3;
            size_t o = (size_t)(i + 2) * 32;
            load_chunk(Ab + o, K, uA[st], tid);
            load_chunk(Wb + o, K, uB[st], tid);
            cp_commit();
        }
        int p = i % 3;
        compute_chunk(sA[p], sB[p], wm, wn, lane, acc);
    }

    int g = lane >> 2, tig = lane & 3;
    #pragma unroll
    for (int mi = 0; mi < 4; mi++) {
        #pragma unroll
        for (int ni = 0; ni < 4; ni++) {
            int n = n0 + wn * 32 + ni * 8 + tig * 2;
            float2 bs = make_float2(0.f, 0.f);
            if (bias) bs = *(const float2*)(bias + n);
            #pragma unroll
            for (int hf = 0; hf < 2; hf++) {
                int m = m0 + wm * 64 + mi * 16 + g + hf * 8;
                float2 v = make_float2(acc[mi][ni][hf * 2 + 0] + bs.x,
                                       acc[mi][ni][hf * 2 + 1] + bs.y);
                if (mode < 2) {
                    int t = m >> 6, b = m & 63;
                    *(float2*)&g_pre[dir][(((size_t)b * TT + t) * GG) + n] = v;
                } else {
                    *(float2*)&g_hW[(size_t)m * H2 + n] = v;
                }
            }
        }
    }
}

// ---------------- per-group software barrier ---------------------------------
__device__ __forceinline__ void grid_bar(int grp, unsigned gen) {
    __threadfence();
    __syncthreads();
    if (threadIdx.x == 0) {
        unsigned arrived = atomicAdd(&g_bar_count[grp], 1u) + 1u;
        if (arrived == GRPBLK) {
            g_bar_count[grp] = 0u;
            __threadfence();
            atomicExch(&g_bar_gen[grp], gen + 1u);
        } else {
            while (atomicAdd(&g_bar_gen[grp], 0u) <= gen) __nanosleep(20);
        }
    }
    __syncthreads();
}

// ---------------- persistent recurrence kernel, W resident in SMEM ----------
// 128 blocks (32 j-tiles x 2 t-tiles x 2 dirs), 512 threads, 64 steps.
// 16 warps = 2m x 2n x 4kq (4-way split-K); partials pair-combined in 2 bufs.
__global__ void __launch_bounds__(512) k_mma_rec_p(
    const float* __restrict__ w_hh_f,
    const float* __restrict__ w_hh_b)
{
    extern __shared__ __align__(16) float sm[];
    int dir = blockIdx.z;
    const float* W = dir ? w_hh_b : w_hh_f;
    int j0 = blockIdx.x * 16;
    int m0 = blockIdx.y * 128;
    int grp = dir * 2 + blockIdx.y;
    int tid = threadIdx.x, lane = tid & 31, wid = tid >> 5;
    int wm = wid >> 3;          // 0..1 : 64-row M half
    int wn = (wid >> 2) & 1;    // 0..1 : 32-col N half
    int kq = wid & 3;           // 0..3 : K split

    float* sW = sm;                     // 16 chunks x 64 x LDSS
    float* sA[4];
    unsigned uA[4];
    #pragma unroll
    for (int st = 0; st < 4; st++) {
        sA[st] = sm + W_F + st * ABUF_F;
        uA[st] = smem_u32(sA[st]);
    }
    float* pb0 = sm + W_F;              // partial buffers alias A bufs
    float* pb1 = sm + W_F + PBUF_F;

    // ---- load W once: 16 chunks, gate-grouped rows (512 thr = 1 f4 each) ----
    {
        #pragma unroll
        for (int chunk = 0; chunk < 16; chunk++) {
            unsigned base = smem_u32(sW + chunk * WCHUNK_F);
            int row = tid >> 3;          // 0..63
            int c   = (tid & 7) * 4;
            int grow = (row >> 4) * 512 + j0 + (row & 15);
            cp16(base + (unsigned)((row * LDSS + c) * 4),
                 W + (size_t)grow * HH + chunk * 32 + c);
        }
        cp_commit(); cp_wait0();
        __syncthreads();
    }

    float creg[4];
    #pragma unroll
    for (int q = 0; q < 4; q++) creg[q] = 0.f;

    for (int s = 0; s < BB; s++) {
        int pp = s & 1;
        int b = dir ? (BB - 1 - s) : s;
        const float* Ab = &g_h[pp][dir][0] + (size_t)m0 * HH;

        float acc[4][4][4];
        #pragma unroll
        for (int i = 0; i < 4; i++)
            #pragma unroll
            for (int j = 0; j < 4; j++)
                #pragma unroll
                for (int q = 0; q < 4; q++) acc[i][j][q] = 0.f;

        // preload super-chunk 0 (chunks 0,1)
        load_chunk512(Ab,      HH, uA[0], tid);
        load_chunk512(Ab + 32, HH, uA[1], tid);
        cp_commit();

        #pragma unroll 2
        for (int sc = 0; sc < 8; sc++) {
            cp_wait0();
            __syncthreads();
            if (sc + 1 < 8) {
                int nb = ((sc + 1) & 1) * 2;
                load_chunk512(Ab + (sc + 1) * 64,      HH, uA[nb],     tid);
                load_chunk512(Ab + (sc + 1) * 64 + 32, HH, uA[nb + 1], tid);
                cp_commit();
            }
            int pbx = (sc & 1) * 2;
            compute_rec4(sA[pbx],     sW + (2 * sc)     * WCHUNK_F, wm, wn, kq, lane, acc);
            compute_rec4(sA[pbx + 1], sW + (2 * sc + 1) * WCHUNK_F, wm, wn, kq, lane, acc);
        }
        __syncthreads();

        // combine 4 split-K partials pairwise into pb0 (kq 0,1) and pb1 (kq 2,3)
        int g = lane >> 2, tig = lane & 3;
        if (kq == 0 || kq == 2) {
            float* pb = (kq == 0) ? pb0 : pb1;
            #pragma unroll
            for (int mi = 0; mi < 4; mi++) {
                #pragma unroll
                for (int ni = 0; ni < 4; ni++) {
                    int col = wn * 32 + ni * 8 + tig * 2;
                    #pragma unroll
                    for (int hf = 0; hf < 2; hf++) {
                        int row = wm * 64 + mi * 16 + g + hf * 8;
                        pb[row * GBSR + col]     = acc[mi][ni][hf * 2 + 0];
                        pb[row * GBSR + col + 1] = acc[mi][ni][hf * 2 + 1];
                    }
                }
            }
        }
        __syncthreads();
        if (kq == 1 || kq == 3) {
            float* pb = (kq == 1) ? pb0 : pb1;
            #pragma unroll
            for (int mi = 0; mi < 4; mi++) {
                #pragma unroll
                for (int ni = 0; ni < 4; ni++) {
                    int col = wn * 32 + ni * 8 + tig * 2;
                    #pragma unroll
                    for (int hf = 0; hf < 2; hf++) {
                        int row = wm * 64 + mi * 16 + g + hf * 8;
                        pb[row * GBSR + col]     += acc[mi][ni][hf * 2 + 0];
                        pb[row * GBSR + col + 1] += acc[mi][ni][hf * 2 + 1];
                    }
                }
            }
        }
        __syncthreads();

        // fused LSTM cell update: 128 t x 16 j items, 4 per thread, c in regs
        #pragma unroll
        for (int it = 0; it < 4; it++) {
            int id = tid + it * 512;
            int tl = id >> 4, jj = id & 15;
            int tg = m0 + tl;
            int jg = j0 + jj;
            size_t preb = ((size_t)b * TT + tg) * GG;
            float vi = pb0[tl * GBSR +  0 + jj] + pb1[tl * GBSR +  0 + jj] + g_pre[dir][preb +    0 + jg];
            float vf = pb0[tl * GBSR + 16 + jj] + pb1[tl * GBSR + 16 + jj] + g_pre[dir][preb +  512 + jg];
            float vg = pb0[tl * GBSR + 32 + jj] + pb1[tl * GBSR + 32 + jj] + g_pre[dir][preb + 1024 + jg];
            float vo = pb0[tl * GBSR + 48 + jj] + pb1[tl * GBSR + 48 + jj] + g_pre[dir][preb + 1536 + jg];
            float c  = creg[it];
            float si = fsig(vi);
            float sf = fsig(vf);
            float so = fsig(vo);
            float cn = sf * c + si * ftanh(vg);
            float h  = so * ftanh(cn);
            creg[it] = cn;
            g_h[pp ^ 1][dir][tg * HH + jg] = h;
            g_sents[(((size_t)tg * BB + b) * H2) + dir * HH + jg] = h;
        }

        if (s + 1 < BB) grid_bar(grp, (unsigned)s);
    }
}

// ---------------- transpose W_nov (K-major B for the nn GEMM) ---------------
__global__ void k_transpose(const float* __restrict__ W) {
    __shared__ float ts[32][33];
    int bx = blockIdx.x * 32, by = blockIdx.y * 32;
    int tx = threadIdx.x, ty = threadIdx.y;   // 32 x 8
    #pragma unroll
    for (int q = 0; q < 4; q++)
        ts[ty + 8*q][tx] = W[(size_t)(by + ty + 8*q) * H2 + bx + tx];
    __syncthreads();
    #pragma unroll
    for (int q = 0; q < 4; q++)
        g_WnovT[(size_t)(bx + ty + 8*q) * H2 + by + tx] = ts[tx][ty + 8*q];
}

// ---------------- init -----------------------------------------------------
__global__ void k_zero() {
    int i = blockIdx.x * blockDim.x + threadIdx.x;
    if (i < 4) { g_bar_count[i] = 0u; g_bar_gen[i] = 0u; }
    if (i < 2*TT*HH) {
        (&g_h[0][0][0])[i] = 0.f;    // pingpong slot 0, both dirs
    }
}

// ---------------- doc pipeline ----------------------------------------------
__global__ void k_docmean() {
    int idx = blockIdx.x * blockDim.x + threadIdx.x;
    int b = idx >> 10, h = idx & 1023;
    float s = 0.f;
    for (int t = 0; t < TT; t++) s += g_sents[(((size_t)t*BB + b)*H2) + h];
    g_docmean[b*H2 + h] = s * (1.f/TT);
}

__global__ void k_doc(const float* __restrict__ W_fdoc, const float* __restrict__ b_fdoc) {
    int w = blockIdx.x*8 + (threadIdx.x >> 5);
    int lane = threadIdx.x & 31;
    int b = w >> 10, n = w & 1023;
    const float* wr = &W_fdoc[(size_t)n*H2];
    const float* dm = &g_docmean[b*H2];
    float s = 0.f;
    for (int k = lane; k < H2; k += 32) s += wr[k]*dm[k];
    #pragma unroll
    for (int o = 16; o > 0; o >>= 1) s += __shfl_down_sync(0xffffffffu, s, o);
    if (lane == 0) g_doc[b*H2 + n] = ftanh(s + b_fdoc[n]);
}

__global__ void k_u(const float* __restrict__ W_sal, const float* __restrict__ w_content) {
    int w = blockIdx.x*8 + (threadIdx.x >> 5);
    int lane = threadIdx.x & 31;
    int b = w >> 10, h = w & 1023;
    const float* wr = &W_sal[(size_t)h*H2];
    const float* dc = &g_doc[b*H2];
    float s = 0.f;
    for (int k = lane; k < H2; k += 32) s += wr[k]*dc[k];
    #pragma unroll
    for (int o = 16; o > 0; o >>= 1) s += __shfl_down_sync(0xffffffffu, s, o);
    if (lane == 0) g_u[b*H2 + h] = s + w_content[h];
}

__global__ void k_absp(const float* __restrict__ pos_emb, const float* __restrict__ w_abs) {
    int t = threadIdx.x;
    float s = 0.f;
    for (int p = 0; p < 100; p++) s += pos_emb[t*100 + p]*w_abs[p];
    g_absp[t] = s;
}

__global__ void k_s0(const float* __restrict__ bias) {
    int w = blockIdx.x*8 + (threadIdx.x >> 5);
    int lane = threadIdx.x & 31;
    int b = w >> 8, t = w & 255;
    const float* sp = &g_sents[((size_t)t*BB + b)*H2];
    const float* up = &g_u[b*H2];
    float s = 0.f;
    for (int k = lane; k < H2; k += 32) s += sp[k]*up[k];
    #pragma unroll
    for (int o = 16; o > 0; o >>= 1) s += __shfl_down_sync(0xffffffffu, s, o);
    if (lane == 0) g_s0[b*TT + t] = s + g_absp[t] + bias[0];
}

// ---------------- final sequential scan (independent per b) -----------------
// 2 syncthreads per t-iteration; reduction broadcast computed redundantly.
__global__ void k_scan(float* __restrict__ out) {
    __shared__ float summ[H2];
    __shared__ float red[8];
    int b = blockIdx.x;
    int tid = threadIdx.x;
    int lane = tid & 31, wrp = tid >> 5;
    #pragma unroll
    for (int q = 0; q < 4; q++) summ[tid + q*256] = 0.f;
    __syncthreads();
    for (int t = 0; t < TT; t++) {
        const float* hw = &g_hW[((size_t)t*BB + b)*H2];
        float part = 0.f;
        #pragma unroll
        for (int q = 0; q < 4; q++) {
            int k = tid + q*256;
            part += hw[k]*ftanh(summ[k]);
        }
        #pragma unroll
        for (int o = 16; o > 0; o >>= 1) part += __shfl_down_sync(0xffffffffu, part, o);
        if (lane == 0) red[wrp] = part;
        __syncthreads();
        float nov = red[0] + red[1] + red[2] + red[3]
                  + red[4] + red[5] + red[6] + red[7];
        float prob = fsig(g_s0[b*TT + t] - nov);
        if (tid == 0) out[b*TT + t] = prob;
        const float* sp = &g_sents[((size_t)t*BB + b)*H2];
        #pragma unroll
        for (int q = 0; q < 4; q++) {
            int k = tid + q*256;
            summ[k] += prob * sp[k];
        }
        __syncthreads();
    }
}

// ---------------- launcher ---------------------------------------------------
extern "C" void kernel_launch(void* const* d_in, const int* in_sizes, int n_in,
                              void* d_out, int out_size) {
    const float* emb      = (const float*)d_in[0];
    const float* w_ih_f   = (const float*)d_in[2];
    const float* w_hh_f   = (const float*)d_in[3];
    const float* b_f      = (const float*)d_in[4];
    const float* w_ih_b   = (const float*)d_in[5];
    const float* w_hh_b   = (const float*)d_in[6];
    const float* b_b      = (const float*)d_in[7];
    const float* W_fdoc   = (const float*)d_in[8];
    const float* b_fdoc   = (const float*)d_in[9];
    const float* pos_emb  = (const float*)d_in[10];
    const float* w_content= (const float*)d_in[11];
    const float* W_sal    = (const float*)d_in[12];
    const float* W_nov    = (const float*)d_in[13];
    const float* w_abs    = (const float*)d_in[14];
    const float* bias     = (const float*)d_in[15];
    float* out = (float*)d_out;

    cudaFuncSetAttribute(k_mma_gemm,  cudaFuncAttributeMaxDynamicSharedMemorySize, SMEM_G);
    cudaFuncSetAttribute(k_mma_rec_p, cudaFuncAttributeMaxDynamicSharedMemorySize, SMEM_RP);

    k_zero<<<1024, 256>>>();
    k_transpose<<<dim3(32, 32), dim3(32, 8)>>>(W_nov);

    // input projections, both dirs fused in one launch (grid.z = dir)
    dim3 gpre(GG/128, TB/128, 2);          // 16 x 128 x 2
    k_mma_gemm<<<gpre, 256, SMEM_G>>>(emb, w_ih_f, w_ih_b, b_f, b_b, EE, 0);

    // recurrence: ONE persistent launch, W resident in SMEM, 64 steps
    dim3 grec(HH/16, TT/128, 2);           // 32 x 2 x 2 = 128 blocks
    k_mma_rec_p<<<grec, 512, SMEM_RP>>>(w_hh_f, w_hh_b);

    k_docmean<<<256, 256>>>();
    k_doc<<<8192, 256>>>(W_fdoc, b_fdoc);
    k_u<<<8192, 256>>>(W_sal, w_content);
    k_absp<<<1, 256>>>(pos_emb, w_abs);
    k_s0<<<2048, 256>>>(bias);

    // novelty GEMM
    dim3 gnn(H2/128, TB/128, 1);           // 8 x 128
    k_mma_gemm<<<gnn, 256, SMEM_G>>>(nullptr, nullptr, nullptr, nullptr, nullptr, H2, 2);

    k_scan<<<BB, 256>>>(out);
}

// round 15
// speedup vs baseline: 1.0328x; 1.0194x over previous
#include <cuda_runtime.h>
#include <math.h>

// Problem dims
#define TT 256
#define BB 64
#define EE 768
#define HH 512
#define H2 1024
#define GG 2048            // 4*H
#define TB (TT*BB)         // 16384

// ---------------- scratch (device globals; no allocation allowed) ----------
__device__ float g_pre[2][(size_t)BB*TT*GG];   // [dir][b][t][g]  (bias included)
__device__ float g_h[2][2][TT*HH];             // [pingpong][dir][t*H+j]
__device__ float g_sents[(size_t)TB*H2];       // [t][b][h2]
__device__ float g_hW[(size_t)TB*H2];          // [t][b][k]
__device__ float g_WnovT[(size_t)H2*H2];       // W_nov transposed (K-major)
__device__ float g_docmean[BB*H2];
__device__ float g_doc[BB*H2];
__device__ float g_u[BB*H2];
__device__ float g_absp[TT];
__device__ float g_s0[BB*TT];

// per-group barrier state (4 groups of 32 blocks; reset by k_zero)
__device__ unsigned g_bar_count[4];
__device__ unsigned g_bar_gen[4];
#define GRPBLK 32

// =========================================================================
// mma.sync 3xTF32 GEMM machinery (mask-based fast split)
// =========================================================================
#define LDSS 36                         // smem row stride (floats)
#define TILE_F (128*LDSS)
#define SMEM_G (6*TILE_F*4)             // big GEMM: 3 stages x (A+B) = 110592 B

// persistent rec: W tile 16 chunks x 64 rows x LDSS + 4 A bufs (2 stages x 2)
#define WCHUNK_F (64*LDSS)              // 2304 floats per W chunk
#define W_F      (16*WCHUNK_F)          // 36864 floats = 147456 B
#define ABUF_F   (128*LDSS)             // 4608 floats = 18432 B
#define SMEM_RP  ((W_F + 4*ABUF_F)*4)   // 221184 B
#define GBSR 68

__device__ __forceinline__ unsigned smem_u32(const void* p) {
    unsigned a;
    asm("{ .reg .u64 t; cvta.to.shared.u64 t, %1; cvt.u32.u64 %0, t; }"
        : "=r"(a) : "l"(p));
    return a;
}
__device__ __forceinline__ void cp16(unsigned s, const float* g) {
    asm volatile("cp.async.cg.shared.global [%0], [%1], 16;"
                 :: "r"(s), "l"(__cvta_generic_to_global((void*)g)));
}
__device__ __forceinline__ void cp_commit() {
    asm volatile("cp.async.commit_group;" ::: "memory");
}
__device__ __forceinline__ void cp_wait1() {
    asm volatile("cp.async.wait_group 1;" ::: "memory");
}
__device__ __forceinline__ void cp_wait0() {
    asm volatile("cp.async.wait_group 0;" ::: "memory");
}
__device__ __forceinline__ void mma8(float c[4], const unsigned a[4], const unsigned b[2]) {
    asm volatile(
        "mma.sync.aligned.m16n8k8.row.col.f32.tf32.tf32.f32 "
        "{%0,%1,%2,%3}, {%4,%5,%6,%7}, {%8,%9}, {%0,%1,%2,%3};\n"
        : "+f"(c[0]), "+f"(c[1]), "+f"(c[2]), "+f"(c[3])
        : "r"(a[0]), "r"(a[1]), "r"(a[2]), "r"(a[3]), "r"(b[0]), "r"(b[1]));
}
// fast split: hi = f masked to tf32 mantissa; lo = exact residual
__device__ __forceinline__ void split_tf32(float f, unsigned& hi, unsigned& lo) {
    hi = __float_as_uint(f) & 0xffffe000u;
    lo = __float_as_uint(f - __uint_as_float(hi));
}
// fast saturating sigmoid/tanh via __expf (no inf/inf hazard)
__device__ __forceinline__ float fsig(float x) {
    return 1.f / (1.f + __expf(-x));
}
__device__ __forceinline__ float ftanh(float x) {
    return 1.f - 2.f / (__expf(2.f * x) + 1.f);
}

// load a 128-row x 32-float K-chunk into smem tile (256 threads)
__device__ __forceinline__ void load_chunk(const float* __restrict__ gsrc, int ldg,
                                           unsigned sbase, int tid) {
    int r0 = tid >> 3;
    int c  = (tid & 7) * 4;
    const float* gp = gsrc + (size_t)r0 * ldg + c;
    unsigned sp = sbase + (unsigned)((r0 * LDSS + c) * 4);
    #pragma unroll
    for (int q = 0; q < 4; q++) {
        cp16(sp, gp);
        gp += (size_t)32 * ldg;
        sp += 32 * LDSS * 4;
    }
}

// 256-thread compute: warp tile 64x32 (wm 0..1, wn 0..3) for big GEMM
__device__ __forceinline__ void compute_chunk(const float* sA, const float* sB,
                                              int wm, int wn, int lane,
                                              float acc[4][4][4]) {
    int g = lane >> 2, tig = lane & 3;
    #pragma unroll
    for (int kk = 0; kk < 4; kk++) {
        int k0 = kk * 8 + tig;
        unsigned ah[4][4], al[4][4], bh[4][2], bl[4][2];
        #pragma unroll
        for (int mi = 0; mi < 4; mi++) {
            int ar = wm * 64 + mi * 16 + g;
            split_tf32(sA[ar * LDSS + k0],           ah[mi][0], al[mi][0]);
            split_tf32(sA[(ar + 8) * LDSS + k0],     ah[mi][1], al[mi][1]);
            split_tf32(sA[ar * LDSS + k0 + 4],       ah[mi][2], al[mi][2]);
            split_tf32(sA[(ar + 8) * LDSS + k0 + 4], ah[mi][3], al[mi][3]);
        }
        #pragma unroll
        for (int ni = 0; ni < 4; ni++) {
            int bn = wn * 32 + ni * 8 + g;
            split_tf32(sB[bn * LDSS + k0],     bh[ni][0], bl[ni][0]);
            split_tf32(sB[bn * LDSS + k0 + 4], bh[ni][1], bl[ni][1]);
        }
        #pragma unroll
        for (int mi = 0; mi < 4; mi++)
            #pragma unroll
            for (int ni = 0; ni < 4; ni++) {
                mma8(acc[mi][ni], al[mi], bh[ni]);
                mma8(acc[mi][ni], ah[mi], bl[ni]);
                mma8(acc[mi][ni], ah[mi], bh[ni]);
            }
    }
}

// rec compute: warp tile 64x32 with split-K (kq warps each take 2 of 4 kk)
__device__ __forceinline__ void compute_rec(const float* sA, const float* sB,
                                            int wm, int wn, int kq, int lane,
                                            float acc[4][4][4]) {
    int g = lane >> 2, tig = lane & 3;
    #pragma unroll
    for (int kh = 0; kh < 2; kh++) {
        int k0 = (kq * 2 + kh) * 8 + tig;
        unsigned ah[4][4], al[4][4], bh[4][2], bl[4][2];
        #pragma unroll
        for (int mi = 0; mi < 4; mi++) {
            int ar = wm * 64 + mi * 16 + g;
            split_tf32(sA[ar * LDSS + k0],           ah[mi][0], al[mi][0]);
            split_tf32(sA[(ar + 8) * LDSS + k0],     ah[mi][1], al[mi][1]);
            split_tf32(sA[ar * LDSS + k0 + 4],       ah[mi][2], al[mi][2]);
            split_tf32(sA[(ar + 8) * LDSS + k0 + 4], ah[mi][3], al[mi][3]);
        }
        #pragma unroll
        for (int ni = 0; ni < 4; ni++) {
            int bn = wn * 32 + ni * 8 + g;
            split_tf32(sB[bn * LDSS + k0],     bh[ni][0], bl[ni][0]);
            split_tf32(sB[bn * LDSS + k0 + 4], bh[ni][1], bl[ni][1]);
        }
        #pragma unroll
        for (int mi = 0; mi < 4; mi++)
            #pragma unroll
            for (int ni = 0; ni < 4; ni++) {
                mma8(acc[mi][ni], al[mi], bh[ni]);
                mma8(acc[mi][ni], ah[mi], bl[ni]);
                mma8(acc[mi][ni], ah[mi], bh[ni]);
            }
    }
}

// ---------------- parallel GEMMs ---------------------------------------------
// mode 0: fused input projections, grid.z = dir; mode 2: novelty GEMM
// 3-stage cp.async pipeline, ONE __syncthreads per K-chunk.
__global__ void __launch_bounds__(256, 2) k_mma_gemm(
    const float* __restrict__ A,
    const float* __restrict__ W0,
    const float* __restrict__ W1,
    const float* __restrict__ bias0,
    const float* __restrict__ bias1,
    int K, int mode)
{
    extern __shared__ __align__(16) float sm[];
    int dir = blockIdx.z;
    const float* W;
    const float* bias;
    if (mode == 2) { A = &g_sents[0]; W = &g_WnovT[0]; bias = nullptr; }
    else           { W = dir ? W1 : W0; bias = dir ? bias1 : bias0; }

    float*   sA[3]; float*   sB[3];
    unsigned uA[3]; unsigned uB[3];
    #pragma unroll
    for (int st = 0; st < 3; st++) {
        sA[st] = sm + st * 2 * TILE_F;
        sB[st] = sA[st] + TILE_F;
        uA[st] = smem_u32(sA[st]);
        uB[st] = smem_u32(sB[st]);
    }
    int tid = threadIdx.x, lane = tid & 31, wid = tid >> 5;
    int wm = wid >> 2, wn = wid & 3;
    int n0 = blockIdx.x * 128, m0 = blockIdx.y * 128;
    const float* Ab = A + (size_t)m0 * K;
    const float* Wb = W + (size_t)n0 * K;

    float acc[4][4][4];
    #pragma unroll
    for (int i = 0; i < 4; i++)
        #pragma unroll
        for (int j = 0; j < 4; j++)
            #pragma unroll
            for (int q = 0; q < 4; q++) acc[i][j][q] = 0.f;

    int NC = K >> 5;
    load_chunk(Ab,      K, uA[0], tid); load_chunk(Wb,      K, uB[0], tid); cp_commit();
    load_chunk(Ab + 32, K, uA[1], tid); load_chunk(Wb + 32, K, uB[1], tid); cp_commit();

    for (int i = 0; i < NC; i++) {
        if (i == NC - 1) cp_wait0(); else cp_wait1();
        __syncthreads();
        if (i + 2 < NC) {
            int st = (i + 2) % 3;
            size_t o = (size_t)(i + 2) * 32;
            load_chunk(Ab + o, K, uA[st], tid);
            load_chunk(Wb + o, K, uB[st], tid);
            cp_commit();
        }
        int p = i % 3;
        compute_chunk(sA[p], sB[p], wm, wn, lane, acc);
    }

    int g = lane >> 2, tig = lane & 3;
    #pragma unroll
    for (int mi = 0; mi < 4; mi++) {
        #pragma unroll
        for (int ni = 0; ni < 4; ni++) {
            int n = n0 + wn * 32 + ni * 8 + tig * 2;
            float2 bs = make_float2(0.f, 0.f);
            if (bias) bs = *(const float2*)(bias + n);
            #pragma unroll
            for (int hf = 0; hf < 2; hf++) {
                int m = m0 + wm * 64 + mi * 16 + g + hf * 8;
                float2 v = make_float2(acc[mi][ni][hf * 2 + 0] + bs.x,
                                       acc[mi][ni][hf * 2 + 1] + bs.y);
                if (mode < 2) {
                    int t = m >> 6, b = m & 63;
                    *(float2*)&g_pre[dir][(((size_t)b * TT + t) * GG) + n] = v;
                } else {
                    *(float2*)&g_hW[(size_t)m * H2 + n] = v;
                }
            }
        }
    }
}

// ---------------- per-group software barrier ---------------------------------
__device__ __forceinline__ void grid_bar(int grp, unsigned gen) {
    __threadfence();
    __syncthreads();
    if (threadIdx.x == 0) {
        unsigned arrived = atomicAdd(&g_bar_count[grp], 1u) + 1u;
        if (arrived == GRPBLK) {
            g_bar_count[grp] = 0u;
            __threadfence();
            atomicExch(&g_bar_gen[grp], gen + 1u);
        } else {
            while (atomicAdd(&g_bar_gen[grp], 0u) <= gen) __nanosleep(20);
        }
    }
    __syncthreads();
}

// ---------------- persistent recurrence kernel, W resident in SMEM ----------
// 128 blocks (32 j-tiles x 2 t-tiles x 2 dirs), 256 threads, 64 steps.
// 8 warps = 2m x 2n x 2kq (split-K). A streamed in 64-wide super-chunks.
// g_pre gate pre-acts preloaded into REGISTERS at step start (overlaps MMAs).
__global__ void __launch_bounds__(256) k_mma_rec_p(
    const float* __restrict__ w_hh_f,
    const float* __restrict__ w_hh_b)
{
    extern __shared__ __align__(16) float sm[];
    int dir = blockIdx.z;
    const float* W = dir ? w_hh_b : w_hh_f;
    int j0 = blockIdx.x * 16;
    int m0 = blockIdx.y * 128;
    int grp = dir * 2 + blockIdx.y;
    int tid = threadIdx.x, lane = tid & 31, wid = tid >> 5;
    int wm = wid >> 2;          // 0..1 : 64-row M half
    int wn = (wid >> 1) & 1;    // 0..1 : 32-col N half
    int kq = wid & 1;           // 0..1 : K split

    float* sW = sm;                     // 16 chunks x 64 x LDSS
    float* sA[4];
    unsigned uA[4];
    #pragma unroll
    for (int st = 0; st < 4; st++) {
        sA[st] = sm + W_F + st * ABUF_F;
        uA[st] = smem_u32(sA[st]);
    }
    float* gb = sm + W_F;               // epilogue gate buffer aliases A bufs

    // ---- load W once: 16 chunks, gate-grouped rows ----
    {
        #pragma unroll
        for (int chunk = 0; chunk < 16; chunk++) {
            unsigned base = smem_u32(sW + chunk * WCHUNK_F);
            #pragma unroll
            for (int q = 0; q < 2; q++) {
                int idx = q * 256 + tid;
                int row = idx >> 3;
                int c   = (idx & 7) * 4;
                int grow = (row >> 4) * 512 + j0 + (row & 15);
                cp16(base + (unsigned)((row * LDSS + c) * 4),
                     W + (size_t)grow * HH + chunk * 32 + c);
            }
        }
        cp_commit(); cp_wait0();
        __syncthreads();
    }

    float creg[8];
    #pragma unroll
    for (int q = 0; q < 8; q++) creg[q] = 0.f;

    // epilogue item coordinates (fixed per thread)
    int e_tl = tid >> 4;       // base t_local for it=0; step adds 16 per it
    int e_jj = tid & 15;

    for (int s = 0; s < BB; s++) {
        int pp = s & 1;
        int b = dir ? (BB - 1 - s) : s;
        const float* Ab = &g_h[pp][dir][0] + (size_t)m0 * HH;

        // ---- early REGISTER preload of g_pre gates (overlaps MMA phase) ----
        float pg[8][4];
        {
            const float* pbase = &g_pre[dir][(((size_t)b * TT + m0 + e_tl) * GG) + j0 + e_jj];
            #pragma unroll
            for (int it = 0; it < 8; it++) {
                const float* pp2 = pbase + (size_t)it * 16 * GG;   // tl += 16 per it
                pg[it][0] = __ldg(pp2);
                pg[it][1] = __ldg(pp2 + 512);
                pg[it][2] = __ldg(pp2 + 1024);
                pg[it][3] = __ldg(pp2 + 1536);
            }
        }

        float acc[4][4][4];
        #pragma unroll
        for (int i = 0; i < 4; i++)
            #pragma unroll
            for (int j = 0; j < 4; j++)
                #pragma unroll
                for (int q = 0; q < 4; q++) acc[i][j][q] = 0.f;

        // preload super-chunk 0 (chunks 0,1)
        load_chunk(Ab,      HH, uA[0], tid);
        load_chunk(Ab + 32, HH, uA[1], tid);
        cp_commit();

        #pragma unroll 2
        for (int sc = 0; sc < 8; sc++) {
            cp_wait0();
            __syncthreads();
            if (sc + 1 < 8) {
                int nb = ((sc + 1) & 1) * 2;
                load_chunk(Ab + (sc + 1) * 64,      HH, uA[nb],     tid);
                load_chunk(Ab + (sc + 1) * 64 + 32, HH, uA[nb + 1], tid);
                cp_commit();
            }
            int pb = (sc & 1) * 2;
            compute_rec(sA[pb],     sW + (2 * sc)     * WCHUNK_F, wm, wn, kq, lane, acc);
            compute_rec(sA[pb + 1], sW + (2 * sc + 1) * WCHUNK_F, wm, wn, kq, lane, acc);
        }
        __syncthreads();

        // combine split-K partials in smem gate buffer:
        int g = lane >> 2, tig = lane & 3;
        if (kq == 0) {
            #pragma unroll
            for (int mi = 0; mi < 4; mi++) {
                #pragma unroll
                for (int ni = 0; ni < 4; ni++) {
                    int col = wn * 32 + ni * 8 + tig * 2;
                    #pragma unroll
                    for (int hf = 0; hf < 2; hf++) {
                        int row = wm * 64 + mi * 16 + g + hf * 8;
                        gb[row * GBSR + col]     = acc[mi][ni][hf * 2 + 0];
                        gb[row * GBSR + col + 1] = acc[mi][ni][hf * 2 + 1];
                    }
                }
            }
        }
        __syncthreads();
        if (kq == 1) {
            #pragma unroll
            for (int mi = 0; mi < 4; mi++) {
                #pragma unroll
                for (int ni = 0; ni < 4; ni++) {
                    int col = wn * 32 + ni * 8 + tig * 2;
                    #pragma unroll
                    for (int hf = 0; hf < 2; hf++) {
                        int row = wm * 64 + mi * 16 + g + hf * 8;
                        gb[row * GBSR + col]     += acc[mi][ni][hf * 2 + 0];
                        gb[row * GBSR + col + 1] += acc[mi][ni][hf * 2 + 1];
                    }
                }
            }
        }
        __syncthreads();

        // fused LSTM cell update: 128 t x 16 j items, 8 per thread
        // gate pre-acts from REGISTERS (pg), MMA partials from smem
        #pragma unroll
        for (int it = 0; it < 8; it++) {
            int tl = e_tl + it * 16;
            int tg = m0 + tl;
            int jg = j0 + e_jj;
            float vi = gb[tl * GBSR +  0 + e_jj] + pg[it][0];
            float vf = gb[tl * GBSR + 16 + e_jj] + pg[it][1];
            float vg = gb[tl * GBSR + 32 + e_jj] + pg[it][2];
            float vo = gb[tl * GBSR + 48 + e_jj] + pg[it][3];
            float c  = creg[it];
            float si = fsig(vi);
            float sf = fsig(vf);
            float so = fsig(vo);
            float cn = sf * c + si * ftanh(vg);
            float h  = so * ftanh(cn);
            creg[it] = cn;
            g_h[pp ^ 1][dir][tg * HH + jg] = h;
            g_sents[(((size_t)tg * BB + b) * H2) + dir * HH + jg] = h;
        }

        if (s + 1 < BB) grid_bar(grp, (unsigned)s);
    }
}

// ---------------- transpose W_nov (K-major B for the nn GEMM) ---------------
__global__ void k_transpose(const float* __restrict__ W) {
    __shared__ float ts[32][33];
    int bx = blockIdx.x * 32, by = blockIdx.y * 32;
    int tx = threadIdx.x, ty = threadIdx.y;   // 32 x 8
    #pragma unroll
    for (int q = 0; q < 4; q++)
        ts[ty + 8*q][tx] = W[(size_t)(by + ty + 8*q) * H2 + bx + tx];
    __syncthreads();
    #pragma unroll
    for (int q = 0; q < 4; q++)
        g_WnovT[(size_t)(bx + ty + 8*q) * H2 + by + tx] = ts[tx][ty + 8*q];
}

// ---------------- init -----------------------------------------------------
__global__ void k_zero() {
    int i = blockIdx.x * blockDim.x + threadIdx.x;
    if (i < 4) { g_bar_count[i] = 0u; g_bar_gen[i] = 0u; }
    if (i < 2*TT*HH) {
        (&g_h[0][0][0])[i] = 0.f;    // pingpong slot 0, both dirs
    }
}

// ---------------- doc pipeline ----------------------------------------------
__global__ void k_docmean() {
    int idx = blockIdx.x * blockDim.x + threadIdx.x;
    int b = idx >> 10, h = idx & 1023;
    float s = 0.f;
    for (int t = 0; t < TT; t++) s += g_sents[(((size_t)t*BB + b)*H2) + h];
    g_docmean[b*H2 + h] = s * (1.f/TT);
}

__global__ void k_doc(const float* __restrict__ W_fdoc, const float* __restrict__ b_fdoc) {
    int w = blockIdx.x*8 + (threadIdx.x >> 5);
    int lane = threadIdx.x & 31;
    int b = w >> 10, n = w & 1023;
    const float* wr = &W_fdoc[(size_t)n*H2];
    const float* dm = &g_docmean[b*H2];
    float s = 0.f;
    for (int k = lane; k < H2; k += 32) s += wr[k]*dm[k];
    #pragma unroll
    for (int o = 16; o > 0; o >>= 1) s += __shfl_down_sync(0xffffffffu, s, o);
    if (lane == 0) g_doc[b*H2 + n] = ftanh(s + b_fdoc[n]);
}

__global__ void k_u(const float* __restrict__ W_sal, const float* __restrict__ w_content) {
    int w = blockIdx.x*8 + (threadIdx.x >> 5);
    int lane = threadIdx.x & 31;
    int b = w >> 10, h = w & 1023;
    const float* wr = &W_sal[(size_t)h*H2];
    const float* dc = &g_doc[b*H2];
    float s = 0.f;
    for (int k = lane; k < H2; k += 32) s += wr[k]*dc[k];
    #pragma unroll
    for (int o = 16; o > 0; o >>= 1) s += __shfl_down_sync(0xffffffffu, s, o);
    if (lane == 0) g_u[b*H2 + h] = s + w_content[h];
}

__global__ void k_absp(const float* __restrict__ pos_emb, const float* __restrict__ w_abs) {
    int t = threadIdx.x;
    float s = 0.f;
    for (int p = 0; p < 100; p++) s += pos_emb[t*100 + p]*w_abs[p];
    g_absp[t] = s;
}

__global__ void k_s0(const float* __restrict__ bias) {
    int w = blockIdx.x*8 + (threadIdx.x >> 5);
    int lane = threadIdx.x & 31;
    int b = w >> 8, t = w & 255;
    const float* sp = &g_sents[((size_t)t*BB + b)*H2];
    const float* up = &g_u[b*H2];
    float s = 0.f;
    for (int k = lane; k < H2; k += 32) s += sp[k]*up[k];
    #pragma unroll
    for (int o = 16; o > 0; o >>= 1) s += __shfl_down_sync(0xffffffffu, s, o);
    if (lane == 0) g_s0[b*TT + t] = s + g_absp[t] + bias[0];
}

// ---------------- final sequential scan (independent per b) -----------------
// 2 syncthreads per t-iteration; reduction broadcast computed redundantly.
__global__ void k_scan(float* __restrict__ out) {
    __shared__ float summ[H2];
    __shared__ float red[8];
    int b = blockIdx.x;
    int tid = threadIdx.x;
    int lane = tid & 31, wrp = tid >> 5;
    #pragma unroll
    for (int q = 0; q < 4; q++) summ[tid + q*256] = 0.f;
    __syncthreads();
    for (int t = 0; t < TT; t++) {
        const float* hw = &g_hW[((size_t)t*BB + b)*H2];
        float part = 0.f;
        #pragma unroll
        for (int q = 0; q < 4; q++) {
            int k = tid + q*256;
            part += hw[k]*ftanh(summ[k]);
        }
        #pragma unroll
        for (int o = 16; o > 0; o >>= 1) part += __shfl_down_sync(0xffffffffu, part, o);
        if (lane == 0) red[wrp] = part;
        __syncthreads();
        float nov = red[0] + red[1] + red[2] + red[3]
                  + red[4] + red[5] + red[6] + red[7];
        float prob = fsig(g_s0[b*TT + t] - nov);
        if (tid == 0) out[b*TT + t] = prob;
        const float* sp = &g_sents[((size_t)t*BB + b)*H2];
        #pragma unroll
        for (int q = 0; q < 4; q++) {
            int k = tid + q*256;
            summ[k] += prob * sp[k];
        }
        __syncthreads();
    }
}

// ---------------- launcher ---------------------------------------------------
extern "C" void kernel_launch(void* const* d_in, const int* in_sizes, int n_in,
                              void* d_out, int out_size) {
    const float* emb      = (const float*)d_in[0];
    const float* w_ih_f   = (const float*)d_in[2];
    const float* w_hh_f   = (const float*)d_in[3];
    const float* b_f      = (const float*)d_in[4];
    const float* w_ih_b   = (const float*)d_in[5];
    const float* w_hh_b   = (const float*)d_in[6];
    const float* b_b      = (const float*)d_in[7];
    const float* W_fdoc   = (const float*)d_in[8];
    const float* b_fdoc   = (const float*)d_in[9];
    const float* pos_emb  = (const float*)d_in[10];
    const float* w_content= (const float*)d_in[11];
    const float* W_sal    = (const float*)d_in[12];
    const float* W_nov    = (const float*)d_in[13];
    const float* w_abs    = (const float*)d_in[14];
    const float* bias     = (const float*)d_in[15];
    float* out = (float*)d_out;

    cudaFuncSetAttribute(k_mma_gemm,  cudaFuncAttributeMaxDynamicSharedMemorySize, SMEM_G);
    cudaFuncSetAttribute(k_mma_rec_p, cudaFuncAttributeMaxDynamicSharedMemorySize, SMEM_RP);

    k_zero<<<1024, 256>>>();
    k_transpose<<<dim3(32, 32), dim3(32, 8)>>>(W_nov);

    // input projections, both dirs fused in one launch (grid.z = dir)
    dim3 gpre(GG/128, TB/128, 2);          // 16 x 128 x 2
    k_mma_gemm<<<gpre, 256, SMEM_G>>>(emb, w_ih_f, w_ih_b, b_f, b_b, EE, 0);

    // recurrence: ONE persistent launch, W resident in SMEM, 64 steps
    dim3 grec(HH/16, TT/128, 2);           // 32 x 2 x 2 = 128 blocks
    k_mma_rec_p<<<grec, 256, SMEM_RP>>>(w_hh_f, w_hh_b);

    k_docmean<<<256, 256>>>();
    k_doc<<<8192, 256>>>(W_fdoc, b_fdoc);
    k_u<<<8192, 256>>>(W_sal, w_content);
    k_absp<<<1, 256>>>(pos_emb, w_abs);
    k_s0<<<2048, 256>>>(bias);

    // novelty GEMM
    dim3 gnn(H2/128, TB/128, 1);           // 8 x 128
    k_mma_gemm<<<gnn, 256, SMEM_G>>>(nullptr, nullptr, nullptr, nullptr, nullptr, H2, 2);

    k_scan<<<BB, 256>>>(out);
}

// round 16
// speedup vs baseline: 1.1959x; 1.1579x over previous
#include <cuda_runtime.h>
#include <math.h>

// Problem dims
#define TT 256
#define BB 64
#define EE 768
#define HH 512
#define H2 1024
#define GG 2048            // 4*H
#define TB (TT*BB)         // 16384

// ---------------- scratch (device globals; no allocation allowed) ----------
__device__ float g_pre[2][(size_t)BB*TT*GG];   // [dir][b][t][g]  (bias included)
__device__ float g_h[2][2][TT*HH];             // [pingpong][dir][t*H+j]
__device__ float g_sents[(size_t)TB*H2];       // [t][b][h2]
__device__ float g_hW[(size_t)TB*H2];          // [t][b][k]
__device__ float g_WnovT[(size_t)H2*H2];       // W_nov transposed (K-major)
__device__ float g_docmean[BB*H2];
__device__ float g_doc[BB*H2];
__device__ float g_u[BB*H2];
__device__ float g_absp[TT];
__device__ float g_s0[BB*TT];

// per-group barrier state (4 groups of 32 blocks; reset by k_zero)
__device__ unsigned g_bar_count[4];
__device__ unsigned g_bar_gen[4];
#define GRPBLK 32

// =========================================================================
// mma.sync TF32 GEMM machinery (3x split for rec/nov; 1x rna for pre)
// =========================================================================
#define LDSS 36                         // smem row stride (floats)
#define TILE_F (128*LDSS)
#define SMEM_G (6*TILE_F*4)             // big GEMM: 3 stages x (A+B) = 110592 B

// persistent rec: W tile 16 chunks x 64 rows x LDSS + 4 A bufs (2 stages x 2)
#define WCHUNK_F (64*LDSS)              // 2304 floats per W chunk
#define W_F      (16*WCHUNK_F)          // 36864 floats = 147456 B
#define ABUF_F   (128*LDSS)             // 4608 floats = 18432 B
#define SMEM_RP  ((W_F + 4*ABUF_F)*4)   // 221184 B
#define GBSR 68

__device__ __forceinline__ unsigned smem_u32(const void* p) {
    unsigned a;
    asm("{ .reg .u64 t; cvta.to.shared.u64 t, %1; cvt.u32.u64 %0, t; }"
        : "=r"(a) : "l"(p));
    return a;
}
__device__ __forceinline__ void cp16(unsigned s, const float* g) {
    asm volatile("cp.async.cg.shared.global [%0], [%1], 16;"
                 :: "r"(s), "l"(__cvta_generic_to_global((void*)g)));
}
__device__ __forceinline__ void cp_commit() {
    asm volatile("cp.async.commit_group;" ::: "memory");
}
__device__ __forceinline__ void cp_wait1() {
    asm volatile("cp.async.wait_group 1;" ::: "memory");
}
__device__ __forceinline__ void cp_wait0() {
    asm volatile("cp.async.wait_group 0;" ::: "memory");
}
__device__ __forceinline__ void mma8(float c[4], const unsigned a[4], const unsigned b[2]) {
    asm volatile(
        "mma.sync.aligned.m16n8k8.row.col.f32.tf32.tf32.f32 "
        "{%0,%1,%2,%3}, {%4,%5,%6,%7}, {%8,%9}, {%0,%1,%2,%3};\n"
        : "+f"(c[0]), "+f"(c[1]), "+f"(c[2]), "+f"(c[3])
        : "r"(a[0]), "r"(a[1]), "r"(a[2]), "r"(a[3]), "r"(b[0]), "r"(b[1]));
}
// fast split: hi = f masked to tf32 mantissa; lo = exact residual
__device__ __forceinline__ void split_tf32(float f, unsigned& hi, unsigned& lo) {
    hi = __float_as_uint(f) & 0xffffe000u;
    lo = __float_as_uint(f - __uint_as_float(hi));
}
// single-op tf32 round-to-nearest (for 1x path)
__device__ __forceinline__ unsigned cvt1_tf32(float f) {
    unsigned u;
    asm("cvt.rna.tf32.f32 %0, %1;" : "=r"(u) : "f"(f));
    return u;
}
// fast saturating sigmoid/tanh via __expf (no inf/inf hazard)
__device__ __forceinline__ float fsig(float x) {
    return 1.f / (1.f + __expf(-x));
}
__device__ __forceinline__ float ftanh(float x) {
    return 1.f - 2.f / (__expf(2.f * x) + 1.f);
}

// load a 128-row x 32-float K-chunk into smem tile (256 threads)
__device__ __forceinline__ void load_chunk(const float* __restrict__ gsrc, int ldg,
                                           unsigned sbase, int tid) {
    int r0 = tid >> 3;
    int c  = (tid & 7) * 4;
    const float* gp = gsrc + (size_t)r0 * ldg + c;
    unsigned sp = sbase + (unsigned)((r0 * LDSS + c) * 4);
    #pragma unroll
    for (int q = 0; q < 4; q++) {
        cp16(sp, gp);
        gp += (size_t)32 * ldg;
        sp += 32 * LDSS * 4;
    }
}

// 256-thread compute: warp tile 64x32, 3xTF32 (rec/nov precision)
__device__ __forceinline__ void compute_chunk3(const float* sA, const float* sB,
                                               int wm, int wn, int lane,
                                               float acc[4][4][4]) {
    int g = lane >> 2, tig = lane & 3;
    #pragma unroll
    for (int kk = 0; kk < 4; kk++) {
        int k0 = kk * 8 + tig;
        unsigned ah[4][4], al[4][4], bh[4][2], bl[4][2];
        #pragma unroll
        for (int mi = 0; mi < 4; mi++) {
            int ar = wm * 64 + mi * 16 + g;
            split_tf32(sA[ar * LDSS + k0],           ah[mi][0], al[mi][0]);
            split_tf32(sA[(ar + 8) * LDSS + k0],     ah[mi][1], al[mi][1]);
            split_tf32(sA[ar * LDSS + k0 + 4],       ah[mi][2], al[mi][2]);
            split_tf32(sA[(ar + 8) * LDSS + k0 + 4], ah[mi][3], al[mi][3]);
        }
        #pragma unroll
        for (int ni = 0; ni < 4; ni++) {
            int bn = wn * 32 + ni * 8 + g;
            split_tf32(sB[bn * LDSS + k0],     bh[ni][0], bl[ni][0]);
            split_tf32(sB[bn * LDSS + k0 + 4], bh[ni][1], bl[ni][1]);
        }
        #pragma unroll
        for (int mi = 0; mi < 4; mi++)
            #pragma unroll
            for (int ni = 0; ni < 4; ni++) {
                mma8(acc[mi][ni], al[mi], bh[ni]);
                mma8(acc[mi][ni], ah[mi], bl[ni]);
                mma8(acc[mi][ni], ah[mi], bh[ni]);
            }
    }
}

// 256-thread compute: warp tile 64x32, 1xTF32 rna (pre-GEMM precision)
__device__ __forceinline__ void compute_chunk1(const float* sA, const float* sB,
                                               int wm, int wn, int lane,
                                               float acc[4][4][4]) {
    int g = lane >> 2, tig = lane & 3;
    #pragma unroll
    for (int kk = 0; kk < 4; kk++) {
        int k0 = kk * 8 + tig;
        unsigned af[4][4], bf[4][2];
        #pragma unroll
        for (int mi = 0; mi < 4; mi++) {
            int ar = wm * 64 + mi * 16 + g;
            af[mi][0] = cvt1_tf32(sA[ar * LDSS + k0]);
            af[mi][1] = cvt1_tf32(sA[(ar + 8) * LDSS + k0]);
            af[mi][2] = cvt1_tf32(sA[ar * LDSS + k0 + 4]);
            af[mi][3] = cvt1_tf32(sA[(ar + 8) * LDSS + k0 + 4]);
        }
        #pragma unroll
        for (int ni = 0; ni < 4; ni++) {
            int bn = wn * 32 + ni * 8 + g;
            bf[ni][0] = cvt1_tf32(sB[bn * LDSS + k0]);
            bf[ni][1] = cvt1_tf32(sB[bn * LDSS + k0 + 4]);
        }
        #pragma unroll
        for (int mi = 0; mi < 4; mi++)
            #pragma unroll
            for (int ni = 0; ni < 4; ni++)
                mma8(acc[mi][ni], af[mi], bf[ni]);
    }
}

// rec compute: warp tile 64x32 with split-K (kq warps each take 2 of 4 kk)
__device__ __forceinline__ void compute_rec(const float* sA, const float* sB,
                                            int wm, int wn, int kq, int lane,
                                            float acc[4][4][4]) {
    int g = lane >> 2, tig = lane & 3;
    #pragma unroll
    for (int kh = 0; kh < 2; kh++) {
        int k0 = (kq * 2 + kh) * 8 + tig;
        unsigned ah[4][4], al[4][4], bh[4][2], bl[4][2];
        #pragma unroll
        for (int mi = 0; mi < 4; mi++) {
            int ar = wm * 64 + mi * 16 + g;
            split_tf32(sA[ar * LDSS + k0],           ah[mi][0], al[mi][0]);
            split_tf32(sA[(ar + 8) * LDSS + k0],     ah[mi][1], al[mi][1]);
            split_tf32(sA[ar * LDSS + k0 + 4],       ah[mi][2], al[mi][2]);
            split_tf32(sA[(ar + 8) * LDSS + k0 + 4], ah[mi][3], al[mi][3]);
        }
        #pragma unroll
        for (int ni = 0; ni < 4; ni++) {
            int bn = wn * 32 + ni * 8 + g;
            split_tf32(sB[bn * LDSS + k0],     bh[ni][0], bl[ni][0]);
            split_tf32(sB[bn * LDSS + k0 + 4], bh[ni][1], bl[ni][1]);
        }
        #pragma unroll
        for (int mi = 0; mi < 4; mi++)
            #pragma unroll
            for (int ni = 0; ni < 4; ni++) {
                mma8(acc[mi][ni], al[mi], bh[ni]);
                mma8(acc[mi][ni], ah[mi], bl[ni]);
                mma8(acc[mi][ni], ah[mi], bh[ni]);
            }
    }
}

// ---------------- parallel GEMMs ---------------------------------------------
// ONE_X=true: 1xTF32 (pre projections, mode 0). ONE_X=false: 3xTF32 (nov, mode 2)
template<bool ONE_X>
__global__ void __launch_bounds__(256, 2) k_mma_gemm(
    const float* __restrict__ A,
    const float* __restrict__ W0,
    const float* __restrict__ W1,
    const float* __restrict__ bias0,
    const float* __restrict__ bias1,
    int K, int mode)
{
    extern __shared__ __align__(16) float sm[];
    int dir = blockIdx.z;
    const float* W;
    const float* bias;
    if (mode == 2) { A = &g_sents[0]; W = &g_WnovT[0]; bias = nullptr; }
    else           { W = dir ? W1 : W0; bias = dir ? bias1 : bias0; }

    float*   sA[3]; float*   sB[3];
    unsigned uA[3]; unsigned uB[3];
    #pragma unroll
    for (int st = 0; st < 3; st++) {
        sA[st] = sm + st * 2 * TILE_F;
        sB[st] = sA[st] + TILE_F;
        uA[st] = smem_u32(sA[st]);
        uB[st] = smem_u32(sB[st]);
    }
    int tid = threadIdx.x, lane = tid & 31, wid = tid >> 5;
    int wm = wid >> 2, wn = wid & 3;
    int n0 = blockIdx.x * 128, m0 = blockIdx.y * 128;
    const float* Ab = A + (size_t)m0 * K;
    const float* Wb = W + (size_t)n0 * K;

    float acc[4][4][4];
    #pragma unroll
    for (int i = 0; i < 4; i++)
        #pragma unroll
        for (int j = 0; j < 4; j++)
            #pragma unroll
            for (int q = 0; q < 4; q++) acc[i][j][q] = 0.f;

    int NC = K >> 5;
    load_chunk(Ab,      K, uA[0], tid); load_chunk(Wb,      K, uB[0], tid); cp_commit();
    load_chunk(Ab + 32, K, uA[1], tid); load_chunk(Wb + 32, K, uB[1], tid); cp_commit();

    for (int i = 0; i < NC; i++) {
        if (i == NC - 1) cp_wait0(); else cp_wait1();
        __syncthreads();
        if (i + 2 < NC) {
            int st = (i + 2) % 3;
            size_t o = (size_t)(i + 2) * 32;
            load_chunk(Ab + o, K, uA[st], tid);
            load_chunk(Wb + o, K, uB[st], tid);
            cp_commit();
        }
        int p = i % 3;
        if (ONE_X) compute_chunk1(sA[p], sB[p], wm, wn, lane, acc);
        else       compute_chunk3(sA[p], sB[p], wm, wn, lane, acc);
    }

    int g = lane >> 2, tig = lane & 3;
    #pragma unroll
    for (int mi = 0; mi < 4; mi++) {
        #pragma unroll
        for (int ni = 0; ni < 4; ni++) {
            int n = n0 + wn * 32 + ni * 8 + tig * 2;
            float2 bs = make_float2(0.f, 0.f);
            if (bias) bs = *(const float2*)(bias + n);
            #pragma unroll
            for (int hf = 0; hf < 2; hf++) {
                int m = m0 + wm * 64 + mi * 16 + g + hf * 8;
                float2 v = make_float2(acc[mi][ni][hf * 2 + 0] + bs.x,
                                       acc[mi][ni][hf * 2 + 1] + bs.y);
                if (mode < 2) {
                    int t = m >> 6, b = m & 63;
                    *(float2*)&g_pre[dir][(((size_t)b * TT + t) * GG) + n] = v;
                } else {
                    *(float2*)&g_hW[(size_t)m * H2 + n] = v;
                }
            }
        }
    }
}

// ---------------- per-group software barrier ---------------------------------
__device__ __forceinline__ void grid_bar(int grp, unsigned gen) {
    __threadfence();
    __syncthreads();
    if (threadIdx.x == 0) {
        unsigned arrived = atomicAdd(&g_bar_count[grp], 1u) + 1u;
        if (arrived == GRPBLK) {
            g_bar_count[grp] = 0u;
            __threadfence();
            atomicExch(&g_bar_gen[grp], gen + 1u);
        } else {
            while (atomicAdd(&g_bar_gen[grp], 0u) <= gen) __nanosleep(20);
        }
    }
    __syncthreads();
}

// ---------------- persistent recurrence kernel, W resident in SMEM ----------
// 128 blocks (32 j-tiles x 2 t-tiles x 2 dirs), 256 threads, 64 steps.
// 8 warps = 2m x 2n x 2kq (split-K). A streamed in 64-wide super-chunks.
// g_pre gate pre-acts preloaded into REGISTERS at step start (overlaps MMAs).
__global__ void __launch_bounds__(256) k_mma_rec_p(
    const float* __restrict__ w_hh_f,
    const float* __restrict__ w_hh_b)
{
    extern __shared__ __align__(16) float sm[];
    int dir = blockIdx.z;
    const float* W = dir ? w_hh_b : w_hh_f;
    int j0 = blockIdx.x * 16;
    int m0 = blockIdx.y * 128;
    int grp = dir * 2 + blockIdx.y;
    int tid = threadIdx.x, lane = tid & 31, wid = tid >> 5;
    int wm = wid >> 2;          // 0..1 : 64-row M half
    int wn = (wid >> 1) & 1;    // 0..1 : 32-col N half
    int kq = wid & 1;           // 0..1 : K split

    float* sW = sm;                     // 16 chunks x 64 x LDSS
    float* sA[4];
    unsigned uA[4];
    #pragma unroll
    for (int st = 0; st < 4; st++) {
        sA[st] = sm + W_F + st * ABUF_F;
        uA[st] = smem_u32(sA[st]);
    }
    float* gb = sm + W_F;               // epilogue gate buffer aliases A bufs

    // ---- load W once: 16 chunks, gate-grouped rows ----
    {
        #pragma unroll
        for (int chunk = 0; chunk < 16; chunk++) {
            unsigned base = smem_u32(sW + chunk * WCHUNK_F);
            #pragma unroll
            for (int q = 0; q < 2; q++) {
                int idx = q * 256 + tid;
                int row = idx >> 3;
                int c   = (idx & 7) * 4;
                int grow = (row >> 4) * 512 + j0 + (row & 15);
                cp16(base + (unsigned)((row * LDSS + c) * 4),
                     W + (size_t)grow * HH + chunk * 32 + c);
            }
        }
        cp_commit(); cp_wait0();
        __syncthreads();
    }

    float creg[8];
    #pragma unroll
    for (int q = 0; q < 8; q++) creg[q] = 0.f;

    // epilogue item coordinates (fixed per thread)
    int e_tl = tid >> 4;       // base t_local for it=0; step adds 16 per it
    int e_jj = tid & 15;

    for (int s = 0; s < BB; s++) {
        int pp = s & 1;
        int b = dir ? (BB - 1 - s) : s;
        const float* Ab = &g_h[pp][dir][0] + (size_t)m0 * HH;

        // ---- early REGISTER preload of g_pre gates (overlaps MMA phase) ----
        float pg[8][4];
        {
            const float* pbase = &g_pre[dir][(((size_t)b * TT + m0 + e_tl) * GG) + j0 + e_jj];
            #pragma unroll
            for (int it = 0; it < 8; it++) {
                const float* pp2 = pbase + (size_t)it * 16 * GG;   // tl += 16 per it
                pg[it][0] = __ldg(pp2);
                pg[it][1] = __ldg(pp2 + 512);
                pg[it][2] = __ldg(pp2 + 1024);
                pg[it][3] = __ldg(pp2 + 1536);
            }
        }

        float acc[4][4][4];
        #pragma unroll
        for (int i = 0; i < 4; i++)
            #pragma unroll
            for (int j = 0; j < 4; j++)
                #pragma unroll
                for (int q = 0; q < 4; q++) acc[i][j][q] = 0.f;

        // preload super-chunk 0 (chunks 0,1)
        load_chunk(Ab,      HH, uA[0], tid);
        load_chunk(Ab + 32, HH, uA[1], tid);
        cp_commit();

        #pragma unroll 2
        for (int sc = 0; sc < 8; sc++) {
            cp_wait0();
            __syncthreads();
            if (sc + 1 < 8) {
                int nb = ((sc + 1) & 1) * 2;
                load_chunk(Ab + (sc + 1) * 64,      HH, uA[nb],     tid);
                load_chunk(Ab + (sc + 1) * 64 + 32, HH, uA[nb + 1], tid);
                cp_commit();
            }
            int pb = (sc & 1) * 2;
            compute_rec(sA[pb],     sW + (2 * sc)     * WCHUNK_F, wm, wn, kq, lane, acc);
            compute_rec(sA[pb + 1], sW + (2 * sc + 1) * WCHUNK_F, wm, wn, kq, lane, acc);
        }
        __syncthreads();

        // combine split-K partials in smem gate buffer:
        int g = lane >> 2, tig = lane & 3;
        if (kq == 0) {
            #pragma unroll
            for (int mi = 0; mi < 4; mi++) {
                #pragma unroll
                for (int ni = 0; ni < 4; ni++) {
                    int col = wn * 32 + ni * 8 + tig * 2;
                    #pragma unroll
                    for (int hf = 0; hf < 2; hf++) {
                        int row = wm * 64 + mi * 16 + g + hf * 8;
                        gb[row * GBSR + col]     = acc[mi][ni][hf * 2 + 0];
                        gb[row * GBSR + col + 1] = acc[mi][ni][hf * 2 + 1];
                    }
                }
            }
        }
        __syncthreads();
        if (kq == 1) {
            #pragma unroll
            for (int mi = 0; mi < 4; mi++) {
                #pragma unroll
                for (int ni = 0; ni < 4; ni++) {
                    int col = wn * 32 + ni * 8 + tig * 2;
                    #pragma unroll
                    for (int hf = 0; hf < 2; hf++) {
                        int row = wm * 64 + mi * 16 + g + hf * 8;
                        gb[row * GBSR + col]     += acc[mi][ni][hf * 2 + 0];
                        gb[row * GBSR + col + 1] += acc[mi][ni][hf * 2 + 1];
                    }
                }
            }
        }
        __syncthreads();

        // fused LSTM cell update: 128 t x 16 j items, 8 per thread
        #pragma unroll
        for (int it = 0; it < 8; it++) {
            int tl = e_tl + it * 16;
            int tg = m0 + tl;
            int jg = j0 + e_jj;
            float vi = gb[tl * GBSR +  0 + e_jj] + pg[it][0];
            float vf = gb[tl * GBSR + 16 + e_jj] + pg[it][1];
            float vg = gb[tl * GBSR + 32 + e_jj] + pg[it][2];
            float vo = gb[tl * GBSR + 48 + e_jj] + pg[it][3];
            float c  = creg[it];
            float si = fsig(vi);
            float sf = fsig(vf);
            float so = fsig(vo);
            float cn = sf * c + si * ftanh(vg);
            float h  = so * ftanh(cn);
            creg[it] = cn;
            g_h[pp ^ 1][dir][tg * HH + jg] = h;
            g_sents[(((size_t)tg * BB + b) * H2) + dir * HH + jg] = h;
        }

        if (s + 1 < BB) grid_bar(grp, (unsigned)s);
    }
}

// ---------------- transpose W_nov (K-major B for the nn GEMM) ---------------
__global__ void k_transpose(const float* __restrict__ W) {
    __shared__ float ts[32][33];
    int bx = blockIdx.x * 32, by = blockIdx.y * 32;
    int tx = threadIdx.x, ty = threadIdx.y;   // 32 x 8
    #pragma unroll
    for (int q = 0; q < 4; q++)
        ts[ty + 8*q][tx] = W[(size_t)(by + ty + 8*q) * H2 + bx + tx];
    __syncthreads();
    #pragma unroll
    for (int q = 0; q < 4; q++)
        g_WnovT[(size_t)(bx + ty + 8*q) * H2 + by + tx] = ts[tx][ty + 8*q];
}

// ---------------- init -----------------------------------------------------
__global__ void k_zero() {
    int i = blockIdx.x * blockDim.x + threadIdx.x;
    if (i < 4) { g_bar_count[i] = 0u; g_bar_gen[i] = 0u; }
    if (i < 2*TT*HH) {
        (&g_h[0][0][0])[i] = 0.f;    // pingpong slot 0, both dirs
    }
}

// ---------------- doc pipeline ----------------------------------------------
__global__ void k_docmean() {
    int idx = blockIdx.x * blockDim.x + threadIdx.x;
    int b = idx >> 10, h = idx & 1023;
    float s = 0.f;
    for (int t = 0; t < TT; t++) s += g_sents[(((size_t)t*BB + b)*H2) + h];
    g_docmean[b*H2 + h] = s * (1.f/TT);
}

__global__ void k_doc(const float* __restrict__ W_fdoc, const float* __restrict__ b_fdoc) {
    int w = blockIdx.x*8 + (threadIdx.x >> 5);
    int lane = threadIdx.x & 31;
    int b = w >> 10, n = w & 1023;
    const float* wr = &W_fdoc[(size_t)n*H2];
    const float* dm = &g_docmean[b*H2];
    float s = 0.f;
    for (int k = lane; k < H2; k += 32) s += wr[k]*dm[k];
    #pragma unroll
    for (int o = 16; o > 0; o >>= 1) s += __shfl_down_sync(0xffffffffu, s, o);
    if (lane == 0) g_doc[b*H2 + n] = ftanh(s + b_fdoc[n]);
}

__global__ void k_u(const float* __restrict__ W_sal, const float* __restrict__ w_content) {
    int w = blockIdx.x*8 + (threadIdx.x >> 5);
    int lane = threadIdx.x & 31;
    int b = w >> 10, h = w & 1023;
    const float* wr = &W_sal[(size_t)h*H2];
    const float* dc = &g_doc[b*H2];
    float s = 0.f;
    for (int k = lane; k < H2; k += 32) s += wr[k]*dc[k];
    #pragma unroll
    for (int o = 16; o > 0; o >>= 1) s += __shfl_down_sync(0xffffffffu, s, o);
    if (lane == 0) g_u[b*H2 + h] = s + w_content[h];
}

__global__ void k_absp(const float* __restrict__ pos_emb, const float* __restrict__ w_abs) {
    int t = threadIdx.x;
    float s = 0.f;
    for (int p = 0; p < 100; p++) s += pos_emb[t*100 + p]*w_abs[p];
    g_absp[t] = s;
}

__global__ void k_s0(const float* __restrict__ bias) {
    int w = blockIdx.x*8 + (threadIdx.x >> 5);
    int lane = threadIdx.x & 31;
    int b = w >> 8, t = w & 255;
    const float* sp = &g_sents[((size_t)t*BB + b)*H2];
    const float* up = &g_u[b*H2];
    float s = 0.f;
    for (int k = lane; k < H2; k += 32) s += sp[k]*up[k];
    #pragma unroll
    for (int o = 16; o > 0; o >>= 1) s += __shfl_down_sync(0xffffffffu, s, o);
    if (lane == 0) g_s0[b*TT + t] = s + g_absp[t] + bias[0];
}

// ---------------- final sequential scan (independent per b) -----------------
__global__ void k_scan(float* __restrict__ out) {
    __shared__ float summ[H2];
    __shared__ float red[8];
    int b = blockIdx.x;
    int tid = threadIdx.x;
    int lane = tid & 31, wrp = tid >> 5;
    #pragma unroll
    for (int q = 0; q < 4; q++) summ[tid + q*256] = 0.f;
    __syncthreads();
    for (int t = 0; t < TT; t++) {
        const float* hw = &g_hW[((size_t)t*BB + b)*H2];
        float part = 0.f;
        #pragma unroll
        for (int q = 0; q < 4; q++) {
            int k = tid + q*256;
            part += hw[k]*ftanh(summ[k]);
        }
        #pragma unroll
        for (int o = 16; o > 0; o >>= 1) part += __shfl_down_sync(0xffffffffu, part, o);
        if (lane == 0) red[wrp] = part;
        __syncthreads();
        float nov = red[0] + red[1] + red[2] + red[3]
                  + red[4] + red[5] + red[6] + red[7];
        float prob = fsig(g_s0[b*TT + t] - nov);
        if (tid == 0) out[b*TT + t] = prob;
        const float* sp = &g_sents[((size_t)t*BB + b)*H2];
        #pragma unroll
        for (int q = 0; q < 4; q++) {
            int k = tid + q*256;
            summ[k] += prob * sp[k];
        }
        __syncthreads();
    }
}

// ---------------- launcher ---------------------------------------------------
extern "C" void kernel_launch(void* const* d_in, const int* in_sizes, int n_in,
                              void* d_out, int out_size) {
    const float* emb      = (const float*)d_in[0];
    const float* w_ih_f   = (const float*)d_in[2];
    const float* w_hh_f   = (const float*)d_in[3];
    const float* b_f      = (const float*)d_in[4];
    const float* w_ih_b   = (const float*)d_in[5];
    const float* w_hh_b   = (const float*)d_in[6];
    const float* b_b      = (const float*)d_in[7];
    const float* W_fdoc   = (const float*)d_in[8];
    const float* b_fdoc   = (const float*)d_in[9];
    const float* pos_emb  = (const float*)d_in[10];
    const float* w_content= (const float*)d_in[11];
    const float* W_sal    = (const float*)d_in[12];
    const float* W_nov    = (const float*)d_in[13];
    const float* w_abs    = (const float*)d_in[14];
    const float* bias     = (const float*)d_in[15];
    float* out = (float*)d_out;

    cudaFuncSetAttribute(k_mma_gemm<true>,  cudaFuncAttributeMaxDynamicSharedMemorySize, SMEM_G);
    cudaFuncSetAttribute(k_mma_gemm<false>, cudaFuncAttributeMaxDynamicSharedMemorySize, SMEM_G);
    cudaFuncSetAttribute(k_mma_rec_p, cudaFuncAttributeMaxDynamicSharedMemorySize, SMEM_RP);

    k_zero<<<1024, 256>>>();
    k_transpose<<<dim3(32, 32), dim3(32, 8)>>>(W_nov);

    // input projections (1xTF32 rna), both dirs fused (grid.z = dir)
    dim3 gpre(GG/128, TB/128, 2);          // 16 x 128 x 2
    k_mma_gemm<true><<<gpre, 256, SMEM_G>>>(emb, w_ih_f, w_ih_b, b_f, b_b, EE, 0);

    // recurrence: ONE persistent launch, W resident in SMEM, 64 steps (3xTF32)
    dim3 grec(HH/16, TT/128, 2);           // 32 x 2 x 2 = 128 blocks
    k_mma_rec_p<<<grec, 256, SMEM_RP>>>(w_hh_f, w_hh_b);

    k_docmean<<<256, 256>>>();
    k_doc<<<8192, 256>>>(W_fdoc, b_fdoc);
    k_u<<<8192, 256>>>(W_sal, w_content);
    k_absp<<<1, 256>>>(pos_emb, w_abs);
    k_s0<<<2048, 256>>>(bias);

    // novelty GEMM (3xTF32)
    dim3 gnn(H2/128, TB/128, 1);           // 8 x 128
    k_mma_gemm<false><<<gnn, 256, SMEM_G>>>(nullptr, nullptr, nullptr, nullptr, nullptr, H2, 2);

    k_scan<<<BB, 256>>>(out);
}

// round 17
// speedup vs baseline: 1.2132x; 1.0145x over previous
#include <cuda_runtime.h>
#include <math.h>

// Problem dims
#define TT 256
#define BB 64
#define EE 768
#define HH 512
#define H2 1024
#define GG 2048            // 4*H
#define TB (TT*BB)         // 16384

// ---------------- scratch (device globals; no allocation allowed) ----------
__device__ float g_pre[2][(size_t)BB*TT*GG];   // [dir][b][t][g]  (bias included)
__device__ float g_h[2][2][TT*HH];             // [pingpong][dir][t*H+j]
__device__ float g_sents[(size_t)TB*H2];       // [t][b][h2]
__device__ float g_hW[(size_t)TB*H2];          // [t][b][k]
__device__ float g_WnovT[(size_t)H2*H2];       // W_nov transposed (K-major)
__device__ float g_docmean[BB*H2];
__device__ float g_doc[BB*H2];
__device__ float g_u[BB*H2];
__device__ float g_absp[TT];
__device__ float g_s0[BB*TT];

// per-group barrier state (4 groups of 32 blocks; reset by k_zero)
__device__ unsigned g_bar_count[4];
__device__ unsigned g_bar_gen[4];
#define GRPBLK 32

// =========================================================================
// mma.sync TF32 GEMM machinery (3x split for rec/nov; 1x rna for pre)
// =========================================================================
#define LDSS 36                         // smem row stride (floats)
#define TILE_F (128*LDSS)
#define SMEM_G (6*TILE_F*4)             // big GEMM: 3 stages x (A+B) = 110592 B

// persistent rec: W tile 16 chunks x 64 rows x LDSS + 4 A bufs (2 stages x 2)
#define WCHUNK_F (64*LDSS)              // 2304 floats per W chunk
#define W_F      (16*WCHUNK_F)          // 36864 floats = 147456 B
#define ABUF_F   (128*LDSS)             // 4608 floats = 18432 B
#define SMEM_RP  ((W_F + 4*ABUF_F)*4)   // 221184 B
#define GBSR 68

__device__ __forceinline__ unsigned smem_u32(const void* p) {
    unsigned a;
    asm("{ .reg .u64 t; cvta.to.shared.u64 t, %1; cvt.u32.u64 %0, t; }"
        : "=r"(a) : "l"(p));
    return a;
}
__device__ __forceinline__ void cp16(unsigned s, const float* g) {
    asm volatile("cp.async.cg.shared.global [%0], [%1], 16;"
                 :: "r"(s), "l"(__cvta_generic_to_global((void*)g)));
}
__device__ __forceinline__ void cp_commit() {
    asm volatile("cp.async.commit_group;" ::: "memory");
}
__device__ __forceinline__ void cp_wait1() {
    asm volatile("cp.async.wait_group 1;" ::: "memory");
}
__device__ __forceinline__ void cp_wait0() {
    asm volatile("cp.async.wait_group 0;" ::: "memory");
}
__device__ __forceinline__ void mma8(float c[4], const unsigned a[4], const unsigned b[2]) {
    asm volatile(
        "mma.sync.aligned.m16n8k8.row.col.f32.tf32.tf32.f32 "
        "{%0,%1,%2,%3}, {%4,%5,%6,%7}, {%8,%9}, {%0,%1,%2,%3};\n"
        : "+f"(c[0]), "+f"(c[1]), "+f"(c[2]), "+f"(c[3])
        : "r"(a[0]), "r"(a[1]), "r"(a[2]), "r"(a[3]), "r"(b[0]), "r"(b[1]));
}
// fast split: hi = f masked to tf32 mantissa; lo = exact residual
__device__ __forceinline__ void split_tf32(float f, unsigned& hi, unsigned& lo) {
    hi = __float_as_uint(f) & 0xffffe000u;
    lo = __float_as_uint(f - __uint_as_float(hi));
}
// single-op tf32 round-to-nearest (for 1x path)
__device__ __forceinline__ unsigned cvt1_tf32(float f) {
    unsigned u;
    asm("cvt.rna.tf32.f32 %0, %1;" : "=r"(u) : "f"(f));
    return u;
}
// fast saturating sigmoid/tanh via __expf (no inf/inf hazard)
__device__ __forceinline__ float fsig(float x) {
    return 1.f / (1.f + __expf(-x));
}
__device__ __forceinline__ float ftanh(float x) {
    return 1.f - 2.f / (__expf(2.f * x) + 1.f);
}

// load a 128-row x 32-float K-chunk into smem tile (256 threads)
__device__ __forceinline__ void load_chunk(const float* __restrict__ gsrc, int ldg,
                                           unsigned sbase, int tid) {
    int r0 = tid >> 3;
    int c  = (tid & 7) * 4;
    const float* gp = gsrc + (size_t)r0 * ldg + c;
    unsigned sp = sbase + (unsigned)((r0 * LDSS + c) * 4);
    #pragma unroll
    for (int q = 0; q < 4; q++) {
        cp16(sp, gp);
        gp += (size_t)32 * ldg;
        sp += 32 * LDSS * 4;
    }
}

// 256-thread compute: warp tile 64x32, 3xTF32 (rec/nov precision)
__device__ __forceinline__ void compute_chunk3(const float* sA, const float* sB,
                                               int wm, int wn, int lane,
                                               float acc[4][4][4]) {
    int g = lane >> 2, tig = lane & 3;
    #pragma unroll
    for (int kk = 0; kk < 4; kk++) {
        int k0 = kk * 8 + tig;
        unsigned ah[4][4], al[4][4], bh[4][2], bl[4][2];
        #pragma unroll
        for (int mi = 0; mi < 4; mi++) {
            int ar = wm * 64 + mi * 16 + g;
            split_tf32(sA[ar * LDSS + k0],           ah[mi][0], al[mi][0]);
            split_tf32(sA[(ar + 8) * LDSS + k0],     ah[mi][1], al[mi][1]);
            split_tf32(sA[ar * LDSS + k0 + 4],       ah[mi][2], al[mi][2]);
            split_tf32(sA[(ar + 8) * LDSS + k0 + 4], ah[mi][3], al[mi][3]);
        }
        #pragma unroll
        for (int ni = 0; ni < 4; ni++) {
            int bn = wn * 32 + ni * 8 + g;
            split_tf32(sB[bn * LDSS + k0],     bh[ni][0], bl[ni][0]);
            split_tf32(sB[bn * LDSS + k0 + 4], bh[ni][1], bl[ni][1]);
        }
        #pragma unroll
        for (int mi = 0; mi < 4; mi++)
            #pragma unroll
            for (int ni = 0; ni < 4; ni++) {
                mma8(acc[mi][ni], al[mi], bh[ni]);
                mma8(acc[mi][ni], ah[mi], bl[ni]);
                mma8(acc[mi][ni], ah[mi], bh[ni]);
            }
    }
}

// 256-thread compute: warp tile 64x32, 1xTF32 rna (pre-GEMM precision)
__device__ __forceinline__ void compute_chunk1(const float* sA, const float* sB,
                                               int wm, int wn, int lane,
                                               float acc[4][4][4]) {
    int g = lane >> 2, tig = lane & 3;
    #pragma unroll
    for (int kk = 0; kk < 4; kk++) {
        int k0 = kk * 8 + tig;
        unsigned af[4][4], bf[4][2];
        #pragma unroll
        for (int mi = 0; mi < 4; mi++) {
            int ar = wm * 64 + mi * 16 + g;
            af[mi][0] = cvt1_tf32(sA[ar * LDSS + k0]);
            af[mi][1] = cvt1_tf32(sA[(ar + 8) * LDSS + k0]);
            af[mi][2] = cvt1_tf32(sA[ar * LDSS + k0 + 4]);
            af[mi][3] = cvt1_tf32(sA[(ar + 8) * LDSS + k0 + 4]);
        }
        #pragma unroll
        for (int ni = 0; ni < 4; ni++) {
            int bn = wn * 32 + ni * 8 + g;
            bf[ni][0] = cvt1_tf32(sB[bn * LDSS + k0]);
            bf[ni][1] = cvt1_tf32(sB[bn * LDSS + k0 + 4]);
        }
        #pragma unroll
        for (int mi = 0; mi < 4; mi++)
            #pragma unroll
            for (int ni = 0; ni < 4; ni++)
                mma8(acc[mi][ni], af[mi], bf[ni]);
    }
}

// rec compute: warp tile 64x32 with split-K (kq warps each take 2 of 4 kk)
__device__ __forceinline__ void compute_rec(const float* sA, const float* sB,
                                            int wm, int wn, int kq, int lane,
                                            float acc[4][4][4]) {
    int g = lane >> 2, tig = lane & 3;
    #pragma unroll
    for (int kh = 0; kh < 2; kh++) {
        int k0 = (kq * 2 + kh) * 8 + tig;
        unsigned ah[4][4], al[4][4], bh[4][2], bl[4][2];
        #pragma unroll
        for (int mi = 0; mi < 4; mi++) {
            int ar = wm * 64 + mi * 16 + g;
            split_tf32(sA[ar * LDSS + k0],           ah[mi][0], al[mi][0]);
            split_tf32(sA[(ar + 8) * LDSS + k0],     ah[mi][1], al[mi][1]);
            split_tf32(sA[ar * LDSS + k0 + 4],       ah[mi][2], al[mi][2]);
            split_tf32(sA[(ar + 8) * LDSS + k0 + 4], ah[mi][3], al[mi][3]);
        }
        #pragma unroll
        for (int ni = 0; ni < 4; ni++) {
            int bn = wn * 32 + ni * 8 + g;
            split_tf32(sB[bn * LDSS + k0],     bh[ni][0], bl[ni][0]);
            split_tf32(sB[bn * LDSS + k0 + 4], bh[ni][1], bl[ni][1]);
        }
        #pragma unroll
        for (int mi = 0; mi < 4; mi++)
            #pragma unroll
            for (int ni = 0; ni < 4; ni++) {
                mma8(acc[mi][ni], al[mi], bh[ni]);
                mma8(acc[mi][ni], ah[mi], bl[ni]);
                mma8(acc[mi][ni], ah[mi], bh[ni]);
            }
    }
}

// ---------------- parallel GEMMs ---------------------------------------------
// ONE_X=true: 1xTF32 (pre projections, mode 0). ONE_X=false: 3xTF32 (nov, mode 2)
template<bool ONE_X>
__global__ void __launch_bounds__(256, 2) k_mma_gemm(
    const float* __restrict__ A,
    const float* __restrict__ W0,
    const float* __restrict__ W1,
    const float* __restrict__ bias0,
    const float* __restrict__ bias1,
    int K, int mode)
{
    extern __shared__ __align__(16) float sm[];
    int dir = blockIdx.z;
    const float* W;
    const float* bias;
    if (mode == 2) { A = &g_sents[0]; W = &g_WnovT[0]; bias = nullptr; }
    else           { W = dir ? W1 : W0; bias = dir ? bias1 : bias0; }

    float*   sA[3]; float*   sB[3];
    unsigned uA[3]; unsigned uB[3];
    #pragma unroll
    for (int st = 0; st < 3; st++) {
        sA[st] = sm + st * 2 * TILE_F;
        sB[st] = sA[st] + TILE_F;
        uA[st] = smem_u32(sA[st]);
        uB[st] = smem_u32(sB[st]);
    }
    int tid = threadIdx.x, lane = tid & 31, wid = tid >> 5;
    int wm = wid >> 2, wn = wid & 3;
    int n0 = blockIdx.x * 128, m0 = blockIdx.y * 128;
    const float* Ab = A + (size_t)m0 * K;
    const float* Wb = W + (size_t)n0 * K;

    float acc[4][4][4];
    #pragma unroll
    for (int i = 0; i < 4; i++)
        #pragma unroll
        for (int j = 0; j < 4; j++)
            #pragma unroll
            for (int q = 0; q < 4; q++) acc[i][j][q] = 0.f;

    int NC = K >> 5;
    load_chunk(Ab,      K, uA[0], tid); load_chunk(Wb,      K, uB[0], tid); cp_commit();
    load_chunk(Ab + 32, K, uA[1], tid); load_chunk(Wb + 32, K, uB[1], tid); cp_commit();

    for (int i = 0; i < NC; i++) {
        if (i == NC - 1) cp_wait0(); else cp_wait1();
        __syncthreads();
        if (i + 2 < NC) {
            int st = (i + 2) % 3;
            size_t o = (size_t)(i + 2) * 32;
            load_chunk(Ab + o, K, uA[st], tid);
            load_chunk(Wb + o, K, uB[st], tid);
            cp_commit();
        }
        int p = i % 3;
        if (ONE_X) compute_chunk1(sA[p], sB[p], wm, wn, lane, acc);
        else       compute_chunk3(sA[p], sB[p], wm, wn, lane, acc);
    }

    int g = lane >> 2, tig = lane & 3;
    #pragma unroll
    for (int mi = 0; mi < 4; mi++) {
        #pragma unroll
        for (int ni = 0; ni < 4; ni++) {
            int n = n0 + wn * 32 + ni * 8 + tig * 2;
            float2 bs = make_float2(0.f, 0.f);
            if (bias) bs = *(const float2*)(bias + n);
            #pragma unroll
            for (int hf = 0; hf < 2; hf++) {
                int m = m0 + wm * 64 + mi * 16 + g + hf * 8;
                float2 v = make_float2(acc[mi][ni][hf * 2 + 0] + bs.x,
                                       acc[mi][ni][hf * 2 + 1] + bs.y);
                if (mode < 2) {
                    int t = m >> 6, b = m & 63;
                    *(float2*)&g_pre[dir][(((size_t)b * TT + t) * GG) + n] = v;
                } else {
                    *(float2*)&g_hW[(size_t)m * H2 + n] = v;
                }
            }
        }
    }
}

// ---------------- per-group software barrier (split arrive / wait) ----------
__device__ __forceinline__ void bar_arrive(int grp) {
    __threadfence();
    __syncthreads();
    if (threadIdx.x == 0) {
        unsigned arrived = atomicAdd(&g_bar_count[grp], 1u) + 1u;
        if (arrived == GRPBLK) {
            g_bar_count[grp] = 0u;
            __threadfence();
            atomicAdd(&g_bar_gen[grp], 1u);
        }
    }
}
__device__ __forceinline__ void bar_wait(int grp, unsigned gen) {
    if (threadIdx.x == 0) {
        while (*(volatile unsigned*)&g_bar_gen[grp] <= gen) { }
    }
    __syncthreads();
}

// ---------------- persistent recurrence kernel, W resident in SMEM ----------
// 128 blocks (32 j-tiles x 2 t-tiles x 2 dirs), 256 threads, 64 steps.
// 8 warps = 2m x 2n x 2kq (split-K). A streamed in 64-wide super-chunks.
// g_pre pre-acts preloaded into registers; step 0 skips the MMA phase (h0=0);
// g_sents stores overlap barrier-arrival latency (arrive/store/wait order).
__global__ void __launch_bounds__(256) k_mma_rec_p(
    const float* __restrict__ w_hh_f,
    const float* __restrict__ w_hh_b)
{
    extern __shared__ __align__(16) float sm[];
    int dir = blockIdx.z;
    const float* W = dir ? w_hh_b : w_hh_f;
    int j0 = blockIdx.x * 16;
    int m0 = blockIdx.y * 128;
    int grp = dir * 2 + blockIdx.y;
    int tid = threadIdx.x, lane = tid & 31, wid = tid >> 5;
    int wm = wid >> 2;          // 0..1 : 64-row M half
    int wn = (wid >> 1) & 1;    // 0..1 : 32-col N half
    int kq = wid & 1;           // 0..1 : K split

    float* sW = sm;                     // 16 chunks x 64 x LDSS
    float* sA[4];
    unsigned uA[4];
    #pragma unroll
    for (int st = 0; st < 4; st++) {
        sA[st] = sm + W_F + st * ABUF_F;
        uA[st] = smem_u32(sA[st]);
    }
    float* gb = sm + W_F;               // epilogue gate buffer aliases A bufs

    // ---- load W once: 16 chunks, gate-grouped rows ----
    {
        #pragma unroll
        for (int chunk = 0; chunk < 16; chunk++) {
            unsigned base = smem_u32(sW + chunk * WCHUNK_F);
            #pragma unroll
            for (int q = 0; q < 2; q++) {
                int idx = q * 256 + tid;
                int row = idx >> 3;
                int c   = (idx & 7) * 4;
                int grow = (row >> 4) * 512 + j0 + (row & 15);
                cp16(base + (unsigned)((row * LDSS + c) * 4),
                     W + (size_t)grow * HH + chunk * 32 + c);
            }
        }
        cp_commit(); cp_wait0();
        __syncthreads();
    }

    float creg[8];
    #pragma unroll
    for (int q = 0; q < 8; q++) creg[q] = 0.f;

    // epilogue item coordinates (fixed per thread)
    int e_tl = tid >> 4;       // base t_local for it=0; step adds 16 per it
    int e_jj = tid & 15;

    for (int s = 0; s < BB; s++) {
        int pp = s & 1;
        int b = dir ? (BB - 1 - s) : s;

        // ---- early REGISTER preload of g_pre gates (overlaps MMA phase) ----
        float pg[8][4];
        {
            const float* pbase = &g_pre[dir][(((size_t)b * TT + m0 + e_tl) * GG) + j0 + e_jj];
            #pragma unroll
            for (int it = 0; it < 8; it++) {
                const float* pp2 = pbase + (size_t)it * 16 * GG;   // tl += 16 per it
                pg[it][0] = __ldg(pp2);
                pg[it][1] = __ldg(pp2 + 512);
                pg[it][2] = __ldg(pp2 + 1024);
                pg[it][3] = __ldg(pp2 + 1536);
            }
        }

        float acc[4][4][4];
        #pragma unroll
        for (int i = 0; i < 4; i++)
            #pragma unroll
            for (int j = 0; j < 4; j++)
                #pragma unroll
                for (int q = 0; q < 4; q++) acc[i][j][q] = 0.f;

        if (s > 0) {   // h(-1) = 0: step 0 contributes nothing, acc stays 0
            const float* Ab = &g_h[pp][dir][0] + (size_t)m0 * HH;
            // preload super-chunk 0 (chunks 0,1)
            load_chunk(Ab,      HH, uA[0], tid);
            load_chunk(Ab + 32, HH, uA[1], tid);
            cp_commit();

            #pragma unroll 2
            for (int sc = 0; sc < 8; sc++) {
                cp_wait0();
                __syncthreads();
                if (sc + 1 < 8) {
                    int nb = ((sc + 1) & 1) * 2;
                    load_chunk(Ab + (sc + 1) * 64,      HH, uA[nb],     tid);
                    load_chunk(Ab + (sc + 1) * 64 + 32, HH, uA[nb + 1], tid);
                    cp_commit();
                }
                int pb = (sc & 1) * 2;
                compute_rec(sA[pb],     sW + (2 * sc)     * WCHUNK_F, wm, wn, kq, lane, acc);
                compute_rec(sA[pb + 1], sW + (2 * sc + 1) * WCHUNK_F, wm, wn, kq, lane, acc);
            }
            __syncthreads();
        }

        // combine split-K partials in smem gate buffer:
        int g = lane >> 2, tig = lane & 3;
        if (kq == 0) {
            #pragma unroll
            for (int mi = 0; mi < 4; mi++) {
                #pragma unroll
                for (int ni = 0; ni < 4; ni++) {
                    int col = wn * 32 + ni * 8 + tig * 2;
                    #pragma unroll
                    for (int hf = 0; hf < 2; hf++) {
                        int row = wm * 64 + mi * 16 + g + hf * 8;
                        gb[row * GBSR + col]     = acc[mi][ni][hf * 2 + 0];
                        gb[row * GBSR + col + 1] = acc[mi][ni][hf * 2 + 1];
                    }
                }
            }
        }
        __syncthreads();
        if (kq == 1) {
            #pragma unroll
            for (int mi = 0; mi < 4; mi++) {
                #pragma unroll
                for (int ni = 0; ni < 4; ni++) {
                    int col = wn * 32 + ni * 8 + tig * 2;
                    #pragma unroll
                    for (int hf = 0; hf < 2; hf++) {
                        int row = wm * 64 + mi * 16 + g + hf * 8;
                        gb[row * GBSR + col]     += acc[mi][ni][hf * 2 + 0];
                        gb[row * GBSR + col + 1] += acc[mi][ni][hf * 2 + 1];
                    }
                }
            }
        }
        __syncthreads();

        // fused LSTM cell update: 128 t x 16 j items, 8 per thread
        // gate pre-acts from REGISTERS (pg), MMA partials from smem.
        // Store h to g_h (next-step dependency) FIRST, arrive at barrier,
        // then do g_sents stores (no in-kernel consumer) while others arrive.
        float hval[8];
        #pragma unroll
        for (int it = 0; it < 8; it++) {
            int tl = e_tl + it * 16;
            int tg = m0 + tl;
            int jg = j0 + e_jj;
            float vi = gb[tl * GBSR +  0 + e_jj] + pg[it][0];
            float vf = gb[tl * GBSR + 16 + e_jj] + pg[it][1];
            float vg = gb[tl * GBSR + 32 + e_jj] + pg[it][2];
            float vo = gb[tl * GBSR + 48 + e_jj] + pg[it][3];
            float c  = creg[it];
            float si = fsig(vi);
            float sf = fsig(vf);
            float so = fsig(vo);
            float cn = sf * c + si * ftanh(vg);
            float h  = so * ftanh(cn);
            creg[it] = cn;
            hval[it] = h;
            g_h[pp ^ 1][dir][tg * HH + jg] = h;
        }

        if (s + 1 < BB) bar_arrive(grp);

        #pragma unroll
        for (int it = 0; it < 8; it++) {
            int tg = m0 + e_tl + it * 16;
            g_sents[(((size_t)tg * BB + b) * H2) + dir * HH + j0 + e_jj] = hval[it];
        }

        if (s + 1 < BB) bar_wait(grp, (unsigned)s);
    }
}

// ---------------- transpose W_nov (K-major B for the nn GEMM) ---------------
__global__ void k_transpose(const float* __restrict__ W) {
    __shared__ float ts[32][33];
    int bx = blockIdx.x * 32, by = blockIdx.y * 32;
    int tx = threadIdx.x, ty = threadIdx.y;   // 32 x 8
    #pragma unroll
    for (int q = 0; q < 4; q++)
        ts[ty + 8*q][tx] = W[(size_t)(by + ty + 8*q) * H2 + bx + tx];
    __syncthreads();
    #pragma unroll
    for (int q = 0; q < 4; q++)
        g_WnovT[(size_t)(bx + ty + 8*q) * H2 + by + tx] = ts[tx][ty + 8*q];
}

// ---------------- init -----------------------------------------------------
__global__ void k_zero() {
    int i = threadIdx.x;
    if (i < 4) { g_bar_count[i] = 0u; g_bar_gen[i] = 0u; }
}

// ---------------- doc pipeline ----------------------------------------------
__global__ void k_docmean() {
    int idx = blockIdx.x * blockDim.x + threadIdx.x;
    int b = idx >> 10, h = idx & 1023;
    float s = 0.f;
    for (int t = 0; t < TT; t++) s += g_sents[(((size_t)t*BB + b)*H2) + h];
    g_docmean[b*H2 + h] = s * (1.f/TT);
}

__global__ void k_doc(const float* __restrict__ W_fdoc, const float* __restrict__ b_fdoc) {
    int w = blockIdx.x*8 + (threadIdx.x >> 5);
    int lane = threadIdx.x & 31;
    int b = w >> 10, n = w & 1023;
    const float* wr = &W_fdoc[(size_t)n*H2];
    const float* dm = &g_docmean[b*H2];
    float s = 0.f;
    for (int k = lane; k < H2; k += 32) s += wr[k]*dm[k];
    #pragma unroll
    for (int o = 16; o > 0; o >>= 1) s += __shfl_down_sync(0xffffffffu, s, o);
    if (lane == 0) g_doc[b*H2 + n] = ftanh(s + b_fdoc[n]);
}

__global__ void k_u(const float* __restrict__ W_sal, const float* __restrict__ w_content) {
    int w = blockIdx.x*8 + (threadIdx.x >> 5);
    int lane = threadIdx.x & 31;
    int b = w >> 10, h = w & 1023;
    const float* wr = &W_sal[(size_t)h*H2];
    const float* dc = &g_doc[b*H2];
    float s = 0.f;
    for (int k = lane; k < H2; k += 32) s += wr[k]*dc[k];
    #pragma unroll
    for (int o = 16; o > 0; o >>= 1) s += __shfl_down_sync(0xffffffffu, s, o);
    if (lane == 0) g_u[b*H2 + h] = s + w_content[h];
}

__global__ void k_absp(const float* __restrict__ pos_emb, const float* __restrict__ w_abs) {
    int t = threadIdx.x;
    float s = 0.f;
    for (int p = 0; p < 100; p++) s += pos_emb[t*100 + p]*w_abs[p];
    g_absp[t] = s;
}

__global__ void k_s0(const float* __restrict__ bias) {
    int w = blockIdx.x*8 + (threadIdx.x >> 5);
    int lane = threadIdx.x & 31;
    int b = w >> 8, t = w & 255;
    const float* sp = &g_sents[((size_t)t*BB + b)*H2];
    const float* up = &g_u[b*H2];
    float s = 0.f;
    for (int k = lane; k < H2; k += 32) s += sp[k]*up[k];
    #pragma unroll
    for (int o = 16; o > 0; o >>= 1) s += __shfl_down_sync(0xffffffffu, s, o);
    if (lane == 0) g_s0[b*TT + t] = s + g_absp[t] + bias[0];
}

// ---------------- final sequential scan (independent per b) -----------------
__global__ void k_scan(float* __restrict__ out) {
    __shared__ float summ[H2];
    __shared__ float red[8];
    int b = blockIdx.x;
    int tid = threadIdx.x;
    int lane = tid & 31, wrp = tid >> 5;
    #pragma unroll
    for (int q = 0; q < 4; q++) summ[tid + q*256] = 0.f;
    __syncthreads();
    for (int t = 0; t < TT; t++) {
        const float* hw = &g_hW[((size_t)t*BB + b)*H2];
        float part = 0.f;
        #pragma unroll
        for (int q = 0; q < 4; q++) {
            int k = tid + q*256;
            part += hw[k]*ftanh(summ[k]);
        }
        #pragma unroll
        for (int o = 16; o > 0; o >>= 1) part += __shfl_down_sync(0xffffffffu, part, o);
        if (lane == 0) red[wrp] = part;
        __syncthreads();
        float nov = red[0] + red[1] + red[2] + red[3]
                  + red[4] + red[5] + red[6] + red[7];
        float prob = fsig(g_s0[b*TT + t] - nov);
        if (tid == 0) out[b*TT + t] = prob;
        const float* sp = &g_sents[((size_t)t*BB + b)*H2];
        #pragma unroll
        for (int q = 0; q < 4; q++) {
            int k = tid + q*256;
            summ[k] += prob * sp[k];
        }
        __syncthreads();
    }
}

// ---------------- launcher ---------------------------------------------------
extern "C" void kernel_launch(void* const* d_in, const int* in_sizes, int n_in,
                              void* d_out, int out_size) {
    const float* emb      = (const float*)d_in[0];
    const float* w_ih_f   = (const float*)d_in[2];
    const float* w_hh_f   = (const float*)d_in[3];
    const float* b_f      = (const float*)d_in[4];
    const float* w_ih_b   = (const float*)d_in[5];
    const float* w_hh_b   = (const float*)d_in[6];
    const float* b_b      = (const float*)d_in[7];
    const float* W_fdoc   = (const float*)d_in[8];
    const float* b_fdoc   = (const float*)d_in[9];
    const float* pos_emb  = (const float*)d_in[10];
    const float* w_content= (const float*)d_in[11];
    const float* W_sal    = (const float*)d_in[12];
    const float* W_nov    = (const float*)d_in[13];
    const float* w_abs    = (const float*)d_in[14];
    const float* bias     = (const float*)d_in[15];
    float* out = (float*)d_out;

    cudaFuncSetAttribute(k_mma_gemm<true>,  cudaFuncAttributeMaxDynamicSharedMemorySize, SMEM_G);
    cudaFuncSetAttribute(k_mma_gemm<false>, cudaFuncAttributeMaxDynamicSharedMemorySize, SMEM_G);
    cudaFuncSetAttribute(k_mma_rec_p, cudaFuncAttributeMaxDynamicSharedMemorySize, SMEM_RP);

    k_zero<<<1, 32>>>();
    k_transpose<<<dim3(32, 32), dim3(32, 8)>>>(W_nov);

    // input projections (1xTF32 rna), both dirs fused (grid.z = dir)
    dim3 gpre(GG/128, TB/128, 2);          // 16 x 128 x 2
    k_mma_gemm<true><<<gpre, 256, SMEM_G>>>(emb, w_ih_f, w_ih_b, b_f, b_b, EE, 0);

    // recurrence: ONE persistent launch, W resident in SMEM, 64 steps (3xTF32)
    dim3 grec(HH/16, TT/128, 2);           // 32 x 2 x 2 = 128 blocks
    k_mma_rec_p<<<grec, 256, SMEM_RP>>>(w_hh_f, w_hh_b);

    k_docmean<<<256, 256>>>();
    k_doc<<<8192, 256>>>(W_fdoc, b_fdoc);
    k_u<<<8192, 256>>>(W_sal, w_content);
    k_absp<<<1, 256>>>(pos_emb, w_abs);
    k_s0<<<2048, 256>>>(bias);

    // novelty GEMM (3xTF32)
    dim3 gnn(H2/128, TB/128, 1);           // 8 x 128
    k_mma_gemm<false><<<gnn, 256, SMEM_G>>>(nullptr, nullptr, nullptr, nullptr, nullptr, H2, 2);

    k_scan<<<BB, 256>>>(out);
}